// round 3
// baseline (speedup 1.0000x reference)
#include <cuda_runtime.h>
#include <cuda_bf16.h>

#define BATCH   256
#define HDIM    512
#define EMBD    256
#define CFEAT   512
#define HWSZ    64
#define NSTEP   257
#define XDIM    517
#define KDIM    1029
#define KPAD    1056
#define NROWS   (BATCH*NSTEP)

// ---------------- device scratch ----------------
__device__ float g_hbuf[2][BATCH*HDIM];
__device__ float g_c[BATCH*HDIM];
__device__ float g_xem[BATCH*HWSZ*EMBD];
__device__ float g_xa[2][BATCH*KPAD];
__device__ float g_hid[NSTEP*BATCH*HDIM];
__device__ float g_Kt[CFEAT*9*EMBD];
__device__ float g_Wc[KPAD*2048];
__device__ float g_y[NROWS*128];

// ---------------- FMA-only tanh (Pade 7/6 + Newton reciprocal) ----------------
__device__ __forceinline__ float ftanh(float x){
    float x2 = x*x;
    float p = x*(135135.f + x2*(17325.f + x2*(378.f + x2)));
    float q = 135135.f + x2*(62370.f + x2*(3150.f + x2*28.f));
    float r = __int_as_float(0x7EF311C3u - __float_as_int(q));
    r = r*(2.f - q*r);
    r = r*(2.f - q*r);
    r = r*(2.f - q*r);
    float t = p*r;
    return fmaxf(-1.f, fminf(1.f, t));
}
__device__ __forceinline__ float fsig(float x){
    return 0.5f + 0.5f*ftanh(0.5f*x);
}

// ---------------- weight prep ----------------
__global__ void k_wt(const float* __restrict__ Kc){
    int idx = blockIdx.x*256 + threadIdx.x;       // 1179648 total
    int e = idx & 255, ct = idx >> 8;
    g_Kt[idx] = Kc[e*4608 + ct];                  // g_Kt[ct][e]
}
__global__ void k_wct(const float* __restrict__ Wih, const float* __restrict__ Whh){
    int k = blockIdx.x;                            // 0..1055
    for (int col = threadIdx.x; col < 2048; col += 256){
        int j = col >> 2, g = col & 3;
        int row = g*512 + j;
        float v = 0.f;
        if (k < XDIM)      v = Wih[row*XDIM + k];
        else if (k < KDIM) v = Whh[row*512 + (k - XDIM)];
        g_Wc[k*2048 + col] = v;
    }
}

// ---------------- init hc ----------------
__global__ void k_init(const float* __restrict__ z, const float* __restrict__ W,
                       const float* __restrict__ bias){
    int b = blockIdx.x, tid = threadIdx.x;
    __shared__ float zs[128];
    if (tid < 128) zs[tid] = z[b*128 + tid];
    if (tid < 54){ int buf = tid/27, col = 1029 + tid%27;
                   g_xa[buf][b*KPAD + col] = 0.f; }
    __syncthreads();
    for (int j = tid; j < 1024; j += 256){
        const float4* wr = (const float4*)(W + j*128);
        const float4* zr = (const float4*)zs;
        float acc = bias[j];
        #pragma unroll 8
        for (int k = 0; k < 32; k++){
            float4 w = wr[k], zz = zr[k];
            acc += w.x*zz.x + w.y*zz.y + w.z*zz.z + w.w*zz.w;
        }
        float v = ftanh(acc);
        if (j < 512){ g_hbuf[0][b*512 + j] = v; g_xa[0][b*KPAD + XDIM + j] = v; }
        else          g_c[b*512 + (j - 512)] = v;
    }
}

// ---------------- conv3x3 SAME -> g_xem[b][p][e] ----------------
__global__ void k_conv(const float* __restrict__ bbf, const float* __restrict__ bcf){
    int b = blockIdx.x, tid = threadIdx.x;
    int eg = tid >> 4, pg = tid & 15;
    __shared__ float in_s[4][64];
    __shared__ float w_s[4*9*256];
    float acc[4][16];
    #pragma unroll
    for (int i = 0; i < 4; i++)
        #pragma unroll
        for (int q = 0; q < 16; q++) acc[i][q] = 0.f;
    const float* src = bbf + b*CFEAT*HWSZ;
    for (int c0 = 0; c0 < CFEAT; c0 += 4){
        __syncthreads();
        const float4* ws4 = (const float4*)(g_Kt + c0*9*256);
        float4* wd4 = (float4*)w_s;
        for (int i = tid; i < 2304; i += 256) wd4[i] = ws4[i];
        { int c = tid >> 6, p = tid & 63; in_s[c][p] = src[(c0+c)*64 + p]; }
        __syncthreads();
        #pragma unroll
        for (int c = 0; c < 4; c++){
            #pragma unroll
            for (int tap = 0; tap < 9; tap++){
                int dy = tap/3 - 1, dx = tap%3 - 1;
                float xv[4];
                #pragma unroll
                for (int pp = 0; pp < 4; pp++){
                    int p = pg*4 + pp;
                    int py = (p >> 3) + dy, px = (p & 7) + dx;
                    xv[pp] = (py >= 0 && py < 8 && px >= 0 && px < 8)
                             ? in_s[c][py*8 + px] : 0.f;
                }
                const float4* wv4 = (const float4*)(w_s + (c*9+tap)*256 + eg*16);
                #pragma unroll
                for (int q = 0; q < 4; q++){
                    float4 w = wv4[q];
                    #pragma unroll
                    for (int pp = 0; pp < 4; pp++){
                        acc[pp][q*4+0] += xv[pp]*w.x;
                        acc[pp][q*4+1] += xv[pp]*w.y;
                        acc[pp][q*4+2] += xv[pp]*w.z;
                        acc[pp][q*4+3] += xv[pp]*w.w;
                    }
                }
            }
        }
    }
    #pragma unroll
    for (int pp = 0; pp < 4; pp++){
        int p = pg*4 + pp;
        float4* dst = (float4*)(g_xem + (b*HWSZ + p)*EMBD + eg*16);
        #pragma unroll
        for (int q = 0; q < 4; q++)
            dst[q] = make_float4(acc[pp][q*4+0]+bcf[eg*16+q*4+0],
                                 acc[pp][q*4+1]+bcf[eg*16+q*4+1],
                                 acc[pp][q*4+2]+bcf[eg*16+q*4+2],
                                 acc[pp][q*4+3]+bcf[eg*16+q*4+3]);
    }
}

// ---------------- per-step attention (2 batches / block) ----------------
__global__ void k_attn(int t, int cur,
                       const float* __restrict__ Wch, const float* __restrict__ bch,
                       const float* __restrict__ Watt, const float* __restrict__ batt,
                       const float* __restrict__ bbf, const float* __restrict__ sketch){
    int b0 = blockIdx.x * 2, tid = threadIdx.x;
    __shared__ float h_s[2*512];
    __shared__ float g_s[2][260];
    __shared__ float sc[2][64];

    ((float4*)h_s)[tid] = ((const float4*)(g_hbuf[cur] + b0*512))[tid];
    __syncthreads();
    {
        int e = tid;
        const float4* wr = (const float4*)(Wch + e*512);
        const float4* h0 = (const float4*)h_s;
        const float4* h1 = (const float4*)(h_s + 512);
        float a0 = 0.f, a1 = 0.f;
        #pragma unroll 8
        for (int k = 0; k < 128; k++){
            float4 w = wr[k], x0 = h0[k], x1 = h1[k];
            a0 += w.x*x0.x + w.y*x0.y + w.z*x0.z + w.w*x0.w;
            a1 += w.x*x1.x + w.y*x1.y + w.z*x1.z + w.w*x1.w;
        }
        g_s[0][e] = a0 + bch[e];
        g_s[1][e] = a1 + bch[e];
    }
    __syncthreads();
    {
        int pair = tid >> 1, half = tid & 1;
        int bb = pair >> 6, p = pair & 63;
        const float4* xr = (const float4*)(g_xem + ((b0+bb)*HWSZ + p)*EMBD + half*128);
        const float4* wa = (const float4*)(Watt + half*128);
        const float4* gv4 = (const float4*)(g_s[bb] + half*128);
        float acc = 0.f;
        #pragma unroll 4
        for (int k = 0; k < 32; k++){
            float4 xe = xr[k], w = wa[k], gv = gv4[k];
            acc += ftanh(xe.x+gv.x)*w.x + ftanh(xe.y+gv.y)*w.y
                 + ftanh(xe.z+gv.z)*w.z + ftanh(xe.w+gv.w)*w.w;
        }
        acc += __shfl_xor_sync(0xffffffffu, acc, 1);
        if (half == 0) sc[bb][p] = acc + batt[0];
    }
    __syncthreads();
    if (tid < 64){
        int bb = tid >> 5, lane = tid & 31;
        float v0 = sc[bb][lane], v1 = sc[bb][lane+32];
        float m = fmaxf(v0, v1);
        #pragma unroll
        for (int o = 16; o; o >>= 1) m = fmaxf(m, __shfl_xor_sync(0xffffffffu, m, o));
        float e0 = __expf(v0 - m), e1 = __expf(v1 - m);
        float s = e0 + e1;
        #pragma unroll
        for (int o = 16; o; o >>= 1) s += __shfl_xor_sync(0xffffffffu, s, o);
        float inv = __fdividef(1.f, s);
        sc[bb][lane] = e0*inv; sc[bb][lane+32] = e1*inv;
    }
    __syncthreads();
    #pragma unroll
    for (int bb = 0; bb < 2; bb++){
        #pragma unroll
        for (int cc = 0; cc < 2; cc++){
            int ch = tid + cc*256;
            const float4* fr = (const float4*)(bbf + ((b0+bb)*CFEAT + ch)*HWSZ);
            float acc = 0.f;
            #pragma unroll
            for (int k = 0; k < 16; k++){
                float4 f = fr[k];
                acc += sc[bb][k*4+0]*f.x + sc[bb][k*4+1]*f.y
                     + sc[bb][k*4+2]*f.z + sc[bb][k*4+3]*f.w;
            }
            g_xa[cur][(b0+bb)*KPAD + ch] = acc;
        }
    }
    if (tid < 10){
        int bb = tid / 5, d = tid % 5;
        float v = (t == 0) ? ((d == 2) ? 1.f : 0.f)
                           : sketch[((t-1)*BATCH + (b0+bb))*5 + d];
        g_xa[cur][(b0+bb)*KPAD + 512 + d] = v;
    }
}

// ---------------- fused gates GEMM + LSTM pointwise ----------------
__global__ void k_gates(int t, int cur,
                        const float* __restrict__ bih, const float* __restrict__ bhh){
    int b0 = blockIdx.x * 16;
    int j0 = blockIdx.y * 64;
    int tid = threadIdx.x;
    int j = tid & 63, bg = tid >> 6;
    int lane = tid & 31, warp = tid >> 5;
    __shared__ float xs[32][16];
    __shared__ float ws[32][256];
    float acc[4][4];
    #pragma unroll
    for (int i = 0; i < 4; i++)
        #pragma unroll
        for (int g = 0; g < 4; g++) acc[i][g] = 0.f;

    const float* xa = g_xa[cur];
    for (int k0 = 0; k0 < KDIM; k0 += 32){
        __syncthreads();
        #pragma unroll
        for (int i = 0; i < 4; i++){
            int kk = warp + 8*i;
            const float4* src = (const float4*)(g_Wc + (k0+kk)*2048 + (j0 << 2));
            float4* dst = (float4*)&ws[kk][0];
            dst[lane]      = src[lane];
            dst[lane + 32] = src[lane + 32];
        }
        #pragma unroll
        for (int i = 0; i < 2; i++){
            int li = tid + (i << 8);
            int kk = li & 31, bi = li >> 5;
            xs[kk][bi] = xa[(b0+bi)*KPAD + k0 + kk];
        }
        __syncthreads();
        #pragma unroll
        for (int k = 0; k < 32; k++){
            float4 xv = *(const float4*)&xs[k][bg*4];
            float4 wv = *(const float4*)&ws[k][j*4];
            float xq[4] = {xv.x, xv.y, xv.z, xv.w};
            float wq[4] = {wv.x, wv.y, wv.z, wv.w};
            #pragma unroll
            for (int bb = 0; bb < 4; bb++)
                #pragma unroll
                for (int g = 0; g < 4; g++)
                    acc[bb][g] += xq[bb]*wq[g];
        }
    }
    int jj = j0 + j;
    int nxt = cur ^ 1;
    float bsum[4];
    #pragma unroll
    for (int g = 0; g < 4; g++) bsum[g] = bih[g*512 + jj] + bhh[g*512 + jj];
    #pragma unroll
    for (int bb = 0; bb < 4; bb++){
        int b = b0 + bg*4 + bb;
        float iv = fsig (acc[bb][0] + bsum[0]);
        float fv = fsig (acc[bb][1] + bsum[1]);
        float gv = ftanh(acc[bb][2] + bsum[2]);
        float ov = fsig (acc[bb][3] + bsum[3]);
        float cold = g_c[b*512 + jj];
        float cnew = fv*cold + iv*gv;
        float hnew = ov*ftanh(cnew);
        g_c[b*512 + jj] = cnew;
        g_hbuf[nxt][b*512 + jj] = hnew;
        g_xa[nxt][b*KPAD + XDIM + jj] = hnew;
        g_hid[(t*BATCH + b)*512 + jj] = hnew;
    }
}

// ---------------- final projection ----------------
__global__ void k_proj(const float* __restrict__ Wfc){
    int n0 = blockIdx.x * 64;
    int tid = threadIdx.x;
    int jg = tid & 31, rg = tid >> 5;
    __shared__ float h_s[32][68];
    __shared__ float w_s[32][132];
    float acc[8][4];
    #pragma unroll
    for (int r = 0; r < 8; r++)
        #pragma unroll
        for (int q = 0; q < 4; q++) acc[r][q] = 0.f;
    for (int k0 = 0; k0 < 512; k0 += 32){
        __syncthreads();
        #pragma unroll
        for (int i = 0; i < 8; i++){
            int li = tid + 256*i;
            int r = li >> 5, kk = li & 31;
            int n = n0 + r;
            int b = n / 257, tt = n - b*257;
            h_s[kk][r] = g_hid[(tt*BATCH + b)*512 + k0 + kk];
        }
        #pragma unroll
        for (int i = 0; i < 16; i++){
            int li = tid + 256*i;
            int jrow = li >> 5, kk = li & 31;
            w_s[kk][jrow] = (jrow < 123) ? Wfc[jrow*512 + k0 + kk] : 0.f;
        }
        __syncthreads();
        #pragma unroll
        for (int k = 0; k < 32; k++){
            float4 wv = *(const float4*)&w_s[k][jg*4];
            float4 h0 = *(const float4*)&h_s[k][rg*8];
            float4 h1 = *(const float4*)&h_s[k][rg*8 + 4];
            float hq[8] = {h0.x,h0.y,h0.z,h0.w,h1.x,h1.y,h1.z,h1.w};
            float wq[4] = {wv.x,wv.y,wv.z,wv.w};
            #pragma unroll
            for (int r = 0; r < 8; r++)
                #pragma unroll
                for (int q = 0; q < 4; q++)
                    acc[r][q] += hq[r]*wq[q];
        }
    }
    #pragma unroll
    for (int r = 0; r < 8; r++){
        int n = n0 + rg*8 + r;
        #pragma unroll
        for (int q = 0; q < 4; q++){
            int jc = jg*4 + q;
            if (jc < 123) g_y[n*128 + jc] = acc[r][q];
        }
    }
}

// ---------------- output transforms ----------------
__global__ void k_out(float* __restrict__ out, const float* __restrict__ bfc){
    int n = blockIdx.x*8 + (threadIdx.x >> 5);
    int lane = threadIdx.x & 31;
    const float* y = g_y + n*128;
    const int N = NROWS;
    float pi = (lane < 20) ? (y[3+lane] + bfc[3+lane]) : -3.4e38f;
    float m = pi;
    #pragma unroll
    for (int o = 16; o; o >>= 1) m = fmaxf(m, __shfl_xor_sync(0xffffffffu, m, o));
    float e = (lane < 20) ? __expf(pi - m) : 0.f;
    float s = e;
    #pragma unroll
    for (int o = 16; o; o >>= 1) s += __shfl_xor_sync(0xffffffffu, s, o);
    float inv = __fdividef(1.f, s);
    if (lane < 20){
        out[           n*20 + lane] = e*inv;
        out[  N*20   + n*20 + lane] = y[23 + lane] + bfc[23 + lane];
        out[2*N*20   + n*20 + lane] = y[43 + lane] + bfc[43 + lane];
        out[3*N*20   + n*20 + lane] = __expf(y[63 + lane] + bfc[63 + lane]);
        out[4*N*20   + n*20 + lane] = __expf(y[83 + lane] + bfc[83 + lane]);
        out[5*N*20   + n*20 + lane] = ftanh(y[103 + lane] + bfc[103 + lane]);
    }
    if (lane < 3)
        out[6*N*20 + n*3 + lane] = y[lane] + bfc[lane];
}

extern "C" void kernel_launch(void* const* d_in, const int* in_sizes, int n_in,
                              void* d_out, int out_size){
    const float* bbf    = (const float*)d_in[0];
    const float* z      = (const float*)d_in[1];
    const float* sk     = (const float*)d_in[2];
    const float* Wfc_hc = (const float*)d_in[3];
    const float* bfc_hc = (const float*)d_in[4];
    const float* Wch    = (const float*)d_in[5];
    const float* bch    = (const float*)d_in[6];
    const float* Kcf    = (const float*)d_in[7];
    const float* bcf    = (const float*)d_in[8];
    const float* Watt   = (const float*)d_in[9];
    const float* batt   = (const float*)d_in[10];
    const float* Wih    = (const float*)d_in[11];
    const float* Whh    = (const float*)d_in[12];
    const float* bih    = (const float*)d_in[13];
    const float* bhh    = (const float*)d_in[14];
    const float* Wfcp   = (const float*)d_in[15];
    const float* bfcp   = (const float*)d_in[16];
    float* out = (float*)d_out;

    k_wt  <<<4608, 256>>>(Kcf);
    k_wct <<<1056, 256>>>(Wih, Whh);
    k_init<<<256, 256>>>(z, Wfc_hc, bfc_hc);
    k_conv<<<256, 256>>>(bbf, bcf);
    for (int t = 0; t < NSTEP; t++){
        int cur = t & 1;
        k_attn <<<128, 256>>>(t, cur, Wch, bch, Watt, batt, bbf, sk);
        k_gates<<<dim3(16,8), 256>>>(t, cur, bih, bhh);
    }
    k_proj<<<1028, 256>>>(Wfcp);
    k_out <<<8224, 256>>>(out, bfcp);
}

// round 5
// speedup vs baseline: 1.5687x; 1.5687x over previous
#include <cuda_runtime.h>
#include <cuda_bf16.h>
#include <cstdint>

#define BATCH   256
#define HDIM    512
#define EMBD    256
#define CFEAT   512
#define HWSZ    64
#define NSTEP   257
#define XDIM    517
#define KDIM    1029
#define KP2     1088        // K padded (17 * 64)
#define NKC     17
#define NROWS   (BATCH*NSTEP)

// ---------------- device scratch ----------------
__device__ float g_hbuf[2][BATCH*HDIM];
__device__ float g_c[BATCH*HDIM];
__device__ float g_xem[BATCH*HWSZ*EMBD];
__device__ float g_hid[NSTEP*BATCH*HDIM];
__device__ float g_Kt[CFEAT*9*EMBD];
__device__ float g_y[NROWS*128];
__device__ __nv_bfloat16 g_Ahi[2][BATCH*KP2];   // A rows [att|pt|h|pad]
__device__ __nv_bfloat16 g_Alo[2][BATCH*KP2];
__device__ __nv_bfloat16 g_Bhi[2048*KP2];       // W combined, col=4j+g, K-major
__device__ __nv_bfloat16 g_Blo[2048*KP2];
__device__ float g_bsum[2048];

// ---------------- FMA-only tanh ----------------
__device__ __forceinline__ float ftanh(float x){
    float x2 = x*x;
    float p = x*(135135.f + x2*(17325.f + x2*(378.f + x2)));
    float q = 135135.f + x2*(62370.f + x2*(3150.f + x2*28.f));
    float r = __int_as_float(0x7EF311C3u - __float_as_int(q));
    r = r*(2.f - q*r);
    r = r*(2.f - q*r);
    r = r*(2.f - q*r);
    float t = p*r;
    return fmaxf(-1.f, fminf(1.f, t));
}
__device__ __forceinline__ float fsig(float x){
    return 0.5f + 0.5f*ftanh(0.5f*x);
}

// ---------------- PTX helpers (non-'a' features only) ----------------
__device__ __forceinline__ uint32_t smem_u32(const void* p){
    uint32_t a;
    asm("{ .reg .u64 t; cvta.to.shared.u64 t, %1; cvt.u32.u64 %0, t; }" : "=r"(a) : "l"(p));
    return a;
}
#define CP_ASYNC16(dst, src) \
    asm volatile("cp.async.cg.shared.global [%0], [%1], 16;" :: "r"(dst), "l"(src))
#define CP_COMMIT()  asm volatile("cp.async.commit_group;" ::: "memory")
#define CP_WAIT(n)   asm volatile("cp.async.wait_group %0;" :: "n"(n) : "memory")

__device__ __forceinline__ void ldm_x4(uint32_t* r, uint32_t addr){
    asm volatile("ldmatrix.sync.aligned.m8n8.x4.shared.b16 {%0,%1,%2,%3}, [%4];"
        : "=r"(r[0]), "=r"(r[1]), "=r"(r[2]), "=r"(r[3]) : "r"(addr));
}
__device__ __forceinline__ void ldm_x2(uint32_t* r, uint32_t addr){
    asm volatile("ldmatrix.sync.aligned.m8n8.x2.shared.b16 {%0,%1}, [%2];"
        : "=r"(r[0]), "=r"(r[1]) : "r"(addr));
}
__device__ __forceinline__ void mma_bf16(float* c, const uint32_t* a, const uint32_t* b){
    asm volatile("mma.sync.aligned.m16n8k16.row.col.f32.bf16.bf16.f32 "
        "{%0,%1,%2,%3}, {%4,%5,%6,%7}, {%8,%9}, {%0,%1,%2,%3};"
        : "+f"(c[0]), "+f"(c[1]), "+f"(c[2]), "+f"(c[3])
        : "r"(a[0]), "r"(a[1]), "r"(a[2]), "r"(a[3]), "r"(b[0]), "r"(b[1]));
}

// smem geometry for k_gates_mma (dynamic)
#define MATB     9216          // one 64x72 bf16 matrix
#define BUFB     36864         // Ah|Al|Bh|Bl
#define OFF_BS   73728
#define SMEM_GATES (OFF_BS + 256)

// ---------------- weight prep ----------------
__global__ void k_wt(const float* __restrict__ Kc){
    int idx = blockIdx.x*256 + threadIdx.x;
    int e = idx & 255, ct = idx >> 8;
    g_Kt[idx] = Kc[e*4608 + ct];
}
__global__ void k_wct2(const float* __restrict__ Wih, const float* __restrict__ Whh,
                       const float* __restrict__ bih, const float* __restrict__ bhh){
    int col = blockIdx.x;                       // 0..2047, col = 4j+g
    int j = col >> 2, g = col & 3;
    int row = g*512 + j;
    for (int k = threadIdx.x; k < KP2; k += 256){
        float v = 0.f;
        if (k < XDIM)      v = Wih[row*XDIM + k];
        else if (k < KDIM) v = Whh[row*512 + (k - XDIM)];
        __nv_bfloat16 hi = __float2bfloat16_rn(v);
        g_Bhi[(size_t)col*KP2 + k] = hi;
        g_Blo[(size_t)col*KP2 + k] = __float2bfloat16_rn(v - __bfloat162float(hi));
    }
    if (threadIdx.x == 0) g_bsum[col] = bih[row] + bhh[row];
}

// ---------------- init hc ----------------
__global__ void k_init(const float* __restrict__ z, const float* __restrict__ W,
                       const float* __restrict__ bias){
    int b = blockIdx.x, tid = threadIdx.x;
    __shared__ float zs[128];
    if (tid < 128) zs[tid] = z[b*128 + tid];
    if (tid < 59){
        __nv_bfloat16 zb = __float2bfloat16_rn(0.f);
        g_Ahi[0][b*KP2 + KDIM + tid] = zb;  g_Alo[0][b*KP2 + KDIM + tid] = zb;
        g_Ahi[1][b*KP2 + KDIM + tid] = zb;  g_Alo[1][b*KP2 + KDIM + tid] = zb;
    }
    __syncthreads();
    for (int j = tid; j < 1024; j += 256){
        const float4* wr = (const float4*)(W + j*128);
        const float4* zr = (const float4*)zs;
        float acc = bias[j];
        #pragma unroll 8
        for (int k = 0; k < 32; k++){
            float4 w = wr[k], zz = zr[k];
            acc += w.x*zz.x + w.y*zz.y + w.z*zz.z + w.w*zz.w;
        }
        float v = ftanh(acc);
        if (j < 512){
            g_hbuf[0][b*512 + j] = v;
            __nv_bfloat16 hi = __float2bfloat16_rn(v);
            g_Ahi[0][b*KP2 + XDIM + j] = hi;
            g_Alo[0][b*KP2 + XDIM + j] = __float2bfloat16_rn(v - __bfloat162float(hi));
        } else g_c[b*512 + (j - 512)] = v;
    }
}

// ---------------- conv3x3 SAME -> g_xem[b][p][e] ----------------
__global__ void k_conv(const float* __restrict__ bbf, const float* __restrict__ bcf){
    int b = blockIdx.x, tid = threadIdx.x;
    int eg = tid >> 4, pg = tid & 15;
    __shared__ float in_s[4][64];
    __shared__ float w_s[4*9*256];
    float acc[4][16];
    #pragma unroll
    for (int i = 0; i < 4; i++)
        #pragma unroll
        for (int q = 0; q < 16; q++) acc[i][q] = 0.f;
    const float* src = bbf + b*CFEAT*HWSZ;
    for (int c0 = 0; c0 < CFEAT; c0 += 4){
        __syncthreads();
        const float4* ws4 = (const float4*)(g_Kt + c0*9*256);
        float4* wd4 = (float4*)w_s;
        for (int i = tid; i < 2304; i += 256) wd4[i] = ws4[i];
        { int c = tid >> 6, p = tid & 63; in_s[c][p] = src[(c0+c)*64 + p]; }
        __syncthreads();
        #pragma unroll
        for (int c = 0; c < 4; c++){
            #pragma unroll
            for (int tap = 0; tap < 9; tap++){
                int dy = tap/3 - 1, dx = tap%3 - 1;
                float xv[4];
                #pragma unroll
                for (int pp = 0; pp < 4; pp++){
                    int p = pg*4 + pp;
                    int py = (p >> 3) + dy, px = (p & 7) + dx;
                    xv[pp] = (py >= 0 && py < 8 && px >= 0 && px < 8)
                             ? in_s[c][py*8 + px] : 0.f;
                }
                const float4* wv4 = (const float4*)(w_s + (c*9+tap)*256 + eg*16);
                #pragma unroll
                for (int q = 0; q < 4; q++){
                    float4 w = wv4[q];
                    #pragma unroll
                    for (int pp = 0; pp < 4; pp++){
                        acc[pp][q*4+0] += xv[pp]*w.x;
                        acc[pp][q*4+1] += xv[pp]*w.y;
                        acc[pp][q*4+2] += xv[pp]*w.z;
                        acc[pp][q*4+3] += xv[pp]*w.w;
                    }
                }
            }
        }
    }
    #pragma unroll
    for (int pp = 0; pp < 4; pp++){
        int p = pg*4 + pp;
        float4* dst = (float4*)(g_xem + (b*HWSZ + p)*EMBD + eg*16);
        #pragma unroll
        for (int q = 0; q < 4; q++)
            dst[q] = make_float4(acc[pp][q*4+0]+bcf[eg*16+q*4+0],
                                 acc[pp][q*4+1]+bcf[eg*16+q*4+1],
                                 acc[pp][q*4+2]+bcf[eg*16+q*4+2],
                                 acc[pp][q*4+3]+bcf[eg*16+q*4+3]);
    }
}

// ---------------- per-step attention (2 batches / block) ----------------
__global__ void k_attn(int t, int cur,
                       const float* __restrict__ Wch, const float* __restrict__ bch,
                       const float* __restrict__ Watt, const float* __restrict__ batt,
                       const float* __restrict__ bbf, const float* __restrict__ sketch){
    int b0 = blockIdx.x * 2, tid = threadIdx.x;
    __shared__ float h_s[2*512];
    __shared__ float g_s[2][260];
    __shared__ float sc[2][64];

    ((float4*)h_s)[tid] = ((const float4*)(g_hbuf[cur] + b0*512))[tid];
    __syncthreads();
    {
        int e = tid;
        const float4* wr = (const float4*)(Wch + e*512);
        const float4* h0 = (const float4*)h_s;
        const float4* h1 = (const float4*)(h_s + 512);
        float a0 = 0.f, a1 = 0.f;
        #pragma unroll 8
        for (int k = 0; k < 128; k++){
            float4 w = wr[k], x0 = h0[k], x1 = h1[k];
            a0 += w.x*x0.x + w.y*x0.y + w.z*x0.z + w.w*x0.w;
            a1 += w.x*x1.x + w.y*x1.y + w.z*x1.z + w.w*x1.w;
        }
        g_s[0][e] = a0 + bch[e];
        g_s[1][e] = a1 + bch[e];
    }
    __syncthreads();
    {
        int pair = tid >> 1, half = tid & 1;
        int bb = pair >> 6, p = pair & 63;
        const float4* xr = (const float4*)(g_xem + ((b0+bb)*HWSZ + p)*EMBD + half*128);
        const float4* wa = (const float4*)(Watt + half*128);
        const float4* gv4 = (const float4*)(g_s[bb] + half*128);
        float acc = 0.f;
        #pragma unroll 4
        for (int k = 0; k < 32; k++){
            float4 xe = xr[k], w = wa[k], gv = gv4[k];
            acc += ftanh(xe.x+gv.x)*w.x + ftanh(xe.y+gv.y)*w.y
                 + ftanh(xe.z+gv.z)*w.z + ftanh(xe.w+gv.w)*w.w;
        }
        acc += __shfl_xor_sync(0xffffffffu, acc, 1);
        if (half == 0) sc[bb][p] = acc + batt[0];
    }
    __syncthreads();
    if (tid < 64){
        int bb = tid >> 5, lane = tid & 31;
        float v0 = sc[bb][lane], v1 = sc[bb][lane+32];
        float m = fmaxf(v0, v1);
        #pragma unroll
        for (int o = 16; o; o >>= 1) m = fmaxf(m, __shfl_xor_sync(0xffffffffu, m, o));
        float e0 = __expf(v0 - m), e1 = __expf(v1 - m);
        float s = e0 + e1;
        #pragma unroll
        for (int o = 16; o; o >>= 1) s += __shfl_xor_sync(0xffffffffu, s, o);
        float inv = __fdividef(1.f, s);
        sc[bb][lane] = e0*inv; sc[bb][lane+32] = e1*inv;
    }
    __syncthreads();
    #pragma unroll
    for (int bb = 0; bb < 2; bb++){
        #pragma unroll
        for (int cc = 0; cc < 2; cc++){
            int ch = tid + cc*256;
            const float4* fr = (const float4*)(bbf + ((b0+bb)*CFEAT + ch)*HWSZ);
            float acc = 0.f;
            #pragma unroll
            for (int k = 0; k < 16; k++){
                float4 f = fr[k];
                acc += sc[bb][k*4+0]*f.x + sc[bb][k*4+1]*f.y
                     + sc[bb][k*4+2]*f.z + sc[bb][k*4+3]*f.w;
            }
            __nv_bfloat16 hi = __float2bfloat16_rn(acc);
            g_Ahi[cur][(b0+bb)*KP2 + ch] = hi;
            g_Alo[cur][(b0+bb)*KP2 + ch] = __float2bfloat16_rn(acc - __bfloat162float(hi));
        }
    }
    if (tid < 10){
        int bb = tid / 5, d = tid % 5;
        float v = (t == 0) ? ((d == 2) ? 1.f : 0.f)
                           : sketch[((t-1)*BATCH + (b0+bb))*5 + d];
        __nv_bfloat16 hi = __float2bfloat16_rn(v);
        g_Ahi[cur][(b0+bb)*KP2 + 512 + d] = hi;
        g_Alo[cur][(b0+bb)*KP2 + 512 + d] = __float2bfloat16_rn(v - __bfloat162float(hi));
    }
}

// ---------------- staging: one 64-K chunk of Ah/Al/Bh/Bl into smem ----------
__device__ __forceinline__ void stage_chunk(uint32_t sb, int buf, int kc,
                                            int mb, int nb, int tid, int cur){
    const __nv_bfloat16* bases[4];
    bases[0] = g_Ahi[cur] + (size_t)mb*64*KP2;
    bases[1] = g_Alo[cur] + (size_t)mb*64*KP2;
    bases[2] = g_Bhi     + (size_t)nb*64*KP2;
    bases[3] = g_Blo     + (size_t)nb*64*KP2;
    uint32_t dbase = sb + buf*BUFB;
    #pragma unroll
    for (int mat = 0; mat < 4; mat++){
        const __nv_bfloat16* src0 = bases[mat] + kc*64;
        #pragma unroll
        for (int i = 0; i < 2; i++){
            int idx = tid + i*256;          // 0..511
            int r = idx >> 3, q = idx & 7;
            const __nv_bfloat16* src = src0 + (size_t)r*KP2 + q*8;
            uint32_t dst = dbase + mat*MATB + r*144 + q*16;
            CP_ASYNC16(dst, src);
        }
    }
}

// ---------------- HMMA gates GEMM + fused LSTM epilogue ----------------
__global__ void __launch_bounds__(256)
k_gates_mma(int t, int cur){
    extern __shared__ char sm[];
    int tid = threadIdx.x;
    int wid = tid >> 5, lane = tid & 31;
    int mb = blockIdx.x;                    // 0..3  (64 batch rows)
    int nb = blockIdx.y;                    // 0..31 (64 packed cols = 16 j's)
    uint32_t sb = smem_u32(sm);

    float* bs = (float*)(sm + OFF_BS);
    if (tid < 64) bs[tid] = g_bsum[nb*64 + tid];

    int wm = wid & 1, wn = wid >> 1;        // warp tile: 32 rows x 16 cols
    float acc[2][2][4];
    #pragma unroll
    for (int mi = 0; mi < 2; mi++)
        #pragma unroll
        for (int ni = 0; ni < 2; ni++)
            #pragma unroll
            for (int q = 0; q < 4; q++) acc[mi][ni][q] = 0.f;

    // per-lane ldmatrix base offsets (within a matrix)
    uint32_t aRow = (uint32_t)(wm*32 + (lane & 15));
    uint32_t aCol = (uint32_t)((lane >> 4) * 8);
    uint32_t bRow = (uint32_t)(wn*16 + (lane & 7));
    uint32_t bCol = (uint32_t)(((lane >> 3) & 1) * 8);

    stage_chunk(sb, 0, 0, mb, nb, tid, cur);
    CP_COMMIT();

    for (int kc = 0; kc < NKC; kc++){
        int buf = kc & 1;
        if (kc + 1 < NKC){
            stage_chunk(sb, buf ^ 1, kc + 1, mb, nb, tid, cur);
            CP_COMMIT();
            CP_WAIT(1);
        } else {
            CP_WAIT(0);
        }
        __syncthreads();

        uint32_t base = sb + buf*BUFB;
        #pragma unroll
        for (int ks = 0; ks < 4; ks++){
            uint32_t kb = (uint32_t)(ks*32);    // ks*16 elements * 2B
            uint32_t ah[2][4], al[2][4], bh[2][2], bl[2][2];
            #pragma unroll
            for (int mi = 0; mi < 2; mi++){
                uint32_t ao = (aRow + mi*16)*144 + kb + aCol*2;
                ldm_x4(ah[mi], base + ao);
                ldm_x4(al[mi], base + MATB + ao);
            }
            #pragma unroll
            for (int ni = 0; ni < 2; ni++){
                uint32_t bo = (bRow + ni*8)*144 + kb + bCol*2;
                ldm_x2(bh[ni], base + 2*MATB + bo);
                ldm_x2(bl[ni], base + 3*MATB + bo);
            }
            #pragma unroll
            for (int mi = 0; mi < 2; mi++)
                #pragma unroll
                for (int ni = 0; ni < 2; ni++){
                    mma_bf16(acc[mi][ni], ah[mi], bh[ni]);
                    mma_bf16(acc[mi][ni], ah[mi], bl[ni]);
                    mma_bf16(acc[mi][ni], al[mi], bh[ni]);
                }
        }
        __syncthreads();
    }

    // ---- epilogue: acc -> smem, fused LSTM pointwise ----
    float* Cs = (float*)sm;                 // 64 x 68 fp32 (reuses staging area)
    #pragma unroll
    for (int mi = 0; mi < 2; mi++)
        #pragma unroll
        for (int ni = 0; ni < 2; ni++){
            int r0 = wm*32 + mi*16 + (lane >> 2);
            int c0 = wn*16 + ni*8 + (lane & 3)*2;
            Cs[r0*68 + c0]       = acc[mi][ni][0];
            Cs[r0*68 + c0 + 1]   = acc[mi][ni][1];
            Cs[(r0+8)*68 + c0]     = acc[mi][ni][2];
            Cs[(r0+8)*68 + c0 + 1] = acc[mi][ni][3];
        }
    __syncthreads();

    int nxt = cur ^ 1;
    #pragma unroll
    for (int i = 0; i < 4; i++){
        int idx = tid + i*256;              // 0..1023
        int bl_ = idx >> 4, jl = idx & 15;
        int b = mb*64 + bl_;
        int j = nb*16 + jl;
        float4 g4 = *(const float4*)&Cs[bl_*68 + jl*4];
        float4 b4 = *(const float4*)&bs[jl*4];
        float iv = fsig (g4.x + b4.x);
        float fv = fsig (g4.y + b4.y);
        float gv = ftanh(g4.z + b4.z);
        float ov = fsig (g4.w + b4.w);
        float cold = g_c[b*512 + j];
        float cnew = fv*cold + iv*gv;
        float hnew = ov*ftanh(cnew);
        g_c[b*512 + j] = cnew;
        g_hbuf[nxt][b*512 + j] = hnew;
        g_hid[(t*BATCH + b)*512 + j] = hnew;
        __nv_bfloat16 hi = __float2bfloat16_rn(hnew);
        g_Ahi[nxt][b*KP2 + XDIM + j] = hi;
        g_Alo[nxt][b*KP2 + XDIM + j] = __float2bfloat16_rn(hnew - __bfloat162float(hi));
    }
}

// ---------------- final projection ----------------
__global__ void k_proj(const float* __restrict__ Wfc){
    int n0 = blockIdx.x * 64;
    int tid = threadIdx.x;
    int jg = tid & 31, rg = tid >> 5;
    __shared__ float h_s[32][68];
    __shared__ float w_s[32][132];
    float acc[8][4];
    #pragma unroll
    for (int r = 0; r < 8; r++)
        #pragma unroll
        for (int q = 0; q < 4; q++) acc[r][q] = 0.f;
    for (int k0 = 0; k0 < 512; k0 += 32){
        __syncthreads();
        #pragma unroll
        for (int i = 0; i < 8; i++){
            int li = tid + 256*i;
            int r = li >> 5, kk = li & 31;
            int n = n0 + r;
            int b = n / 257, tt = n - b*257;
            h_s[kk][r] = g_hid[(tt*BATCH + b)*512 + k0 + kk];
        }
        #pragma unroll
        for (int i = 0; i < 16; i++){
            int li = tid + 256*i;
            int jrow = li >> 5, kk = li & 31;
            w_s[kk][jrow] = (jrow < 123) ? Wfc[jrow*512 + k0 + kk] : 0.f;
        }
        __syncthreads();
        #pragma unroll
        for (int k = 0; k < 32; k++){
            float4 wv = *(const float4*)&w_s[k][jg*4];
            float4 h0 = *(const float4*)&h_s[k][rg*8];
            float4 h1 = *(const float4*)&h_s[k][rg*8 + 4];
            float hq[8] = {h0.x,h0.y,h0.z,h0.w,h1.x,h1.y,h1.z,h1.w};
            float wq[4] = {wv.x,wv.y,wv.z,wv.w};
            #pragma unroll
            for (int r = 0; r < 8; r++)
                #pragma unroll
                for (int q = 0; q < 4; q++)
                    acc[r][q] += hq[r]*wq[q];
        }
    }
    #pragma unroll
    for (int r = 0; r < 8; r++){
        int n = n0 + rg*8 + r;
        #pragma unroll
        for (int q = 0; q < 4; q++){
            int jc = jg*4 + q;
            if (jc < 123) g_y[n*128 + jc] = acc[r][q];
        }
    }
}

// ---------------- output transforms ----------------
__global__ void k_out(float* __restrict__ out, const float* __restrict__ bfc){
    int n = blockIdx.x*8 + (threadIdx.x >> 5);
    int lane = threadIdx.x & 31;
    const float* y = g_y + n*128;
    const int N = NROWS;
    float pi = (lane < 20) ? (y[3+lane] + bfc[3+lane]) : -3.4e38f;
    float m = pi;
    #pragma unroll
    for (int o = 16; o; o >>= 1) m = fmaxf(m, __shfl_xor_sync(0xffffffffu, m, o));
    float e = (lane < 20) ? __expf(pi - m) : 0.f;
    float s = e;
    #pragma unroll
    for (int o = 16; o; o >>= 1) s += __shfl_xor_sync(0xffffffffu, s, o);
    float inv = __fdividef(1.f, s);
    if (lane < 20){
        out[           n*20 + lane] = e*inv;
        out[  N*20   + n*20 + lane] = y[23 + lane] + bfc[23 + lane];
        out[2*N*20   + n*20 + lane] = y[43 + lane] + bfc[43 + lane];
        out[3*N*20   + n*20 + lane] = __expf(y[63 + lane] + bfc[63 + lane]);
        out[4*N*20   + n*20 + lane] = __expf(y[83 + lane] + bfc[83 + lane]);
        out[5*N*20   + n*20 + lane] = ftanh(y[103 + lane] + bfc[103 + lane]);
    }
    if (lane < 3)
        out[6*N*20 + n*3 + lane] = y[lane] + bfc[lane];
}

extern "C" void kernel_launch(void* const* d_in, const int* in_sizes, int n_in,
                              void* d_out, int out_size){
    const float* bbf    = (const float*)d_in[0];
    const float* z      = (const float*)d_in[1];
    const float* sk     = (const float*)d_in[2];
    const float* Wfc_hc = (const float*)d_in[3];
    const float* bfc_hc = (const float*)d_in[4];
    const float* Wch    = (const float*)d_in[5];
    const float* bch    = (const float*)d_in[6];
    const float* Kcf    = (const float*)d_in[7];
    const float* bcf    = (const float*)d_in[8];
    const float* Watt   = (const float*)d_in[9];
    const float* batt   = (const float*)d_in[10];
    const float* Wih    = (const float*)d_in[11];
    const float* Whh    = (const float*)d_in[12];
    const float* bih    = (const float*)d_in[13];
    const float* bhh    = (const float*)d_in[14];
    const float* Wfcp   = (const float*)d_in[15];
    const float* bfcp   = (const float*)d_in[16];
    float* out = (float*)d_out;

    static int smem_set = 0;
    if (!smem_set){
        cudaFuncSetAttribute(k_gates_mma, cudaFuncAttributeMaxDynamicSharedMemorySize, SMEM_GATES);
        smem_set = 1;
    }

    k_wt   <<<4608, 256>>>(Kcf);
    k_wct2 <<<2048, 256>>>(Wih, Whh, bih, bhh);
    k_init <<<256, 256>>>(z, Wfc_hc, bfc_hc);
    k_conv <<<256, 256>>>(bbf, bcf);
    for (int t = 0; t < NSTEP; t++){
        int cur = t & 1;
        k_attn <<<128, 256>>>(t, cur, Wch, bch, Watt, batt, bbf, sk);
        k_gates_mma<<<dim3(4, 32), 256, SMEM_GATES>>>(t, cur);
    }
    k_proj<<<1028, 256>>>(Wfcp);
    k_out <<<8224, 256>>>(out, bfcp);
}

// round 8
// speedup vs baseline: 2.1877x; 1.3947x over previous
#include <cuda_runtime.h>
#include <cuda_bf16.h>
#include <cstdint>

#define BATCH   256
#define HDIM    512
#define EMBD    256
#define CFEAT   512
#define HWSZ    64
#define NSTEP   257
#define KDIM    1029
#define KP2     1088        // K padded (17 * 64)
#define NCOL    2304        // 2048 gate cols + 256 g_em cols
#define NROWS   (BATCH*NSTEP)

// ---------------- device scratch ----------------
__device__ float g_c[BATCH*HDIM];
__device__ float g_xem[BATCH*HWSZ*EMBD];
__device__ float g_hid[NSTEP*BATCH*HDIM];
__device__ float g_Kt[CFEAT*9*EMBD];
__device__ float g_y[NROWS*128];
__device__ float g_part[BATCH*2048];            // partial gates (h-part)
__device__ float g_gem[BATCH*EMBD];             // g_em + bias
__device__ __nv_bfloat16 g_Ahi[BATCH*KP2];      // A rows [h|att|pt|pad]
__device__ __nv_bfloat16 g_Alo[BATCH*KP2];
__device__ __nv_bfloat16 g_Bhi[(size_t)NCOL*KP2];
__device__ __nv_bfloat16 g_Blo[(size_t)NCOL*KP2];
__device__ float g_bsum[2048];

// ---------------- FMA-only tanh ----------------
__device__ __forceinline__ float ftanh(float x){
    float x2 = x*x;
    float p = x*(135135.f + x2*(17325.f + x2*(378.f + x2)));
    float q = 135135.f + x2*(62370.f + x2*(3150.f + x2*28.f));
    float r = __int_as_float(0x7EF311C3u - __float_as_int(q));
    r = r*(2.f - q*r);
    r = r*(2.f - q*r);
    r = r*(2.f - q*r);
    float t = p*r;
    return fmaxf(-1.f, fminf(1.f, t));
}
__device__ __forceinline__ float fsig(float x){
    return 0.5f + 0.5f*ftanh(0.5f*x);
}

// ---------------- PTX helpers ----------------
__device__ __forceinline__ uint32_t smem_u32(const void* p){
    uint32_t a;
    asm("{ .reg .u64 t; cvta.to.shared.u64 t, %1; cvt.u32.u64 %0, t; }" : "=r"(a) : "l"(p));
    return a;
}
#define CP_ASYNC16(dst, src) \
    asm volatile("cp.async.cg.shared.global [%0], [%1], 16;" :: "r"(dst), "l"(src))
#define CP_COMMIT()  asm volatile("cp.async.commit_group;" ::: "memory")
#define CP_WAIT(n)   asm volatile("cp.async.wait_group %0;" :: "n"(n) : "memory")

__device__ __forceinline__ void ldm_x4(uint32_t* r, uint32_t addr){
    asm volatile("ldmatrix.sync.aligned.m8n8.x4.shared.b16 {%0,%1,%2,%3}, [%4];"
        : "=r"(r[0]), "=r"(r[1]), "=r"(r[2]), "=r"(r[3]) : "r"(addr));
}
__device__ __forceinline__ void ldm_x2(uint32_t* r, uint32_t addr){
    asm volatile("ldmatrix.sync.aligned.m8n8.x2.shared.b16 {%0,%1}, [%2];"
        : "=r"(r[0]), "=r"(r[1]) : "r"(addr));
}
__device__ __forceinline__ void mma_bf16(float* c, const uint32_t* a, const uint32_t* b){
    asm volatile("mma.sync.aligned.m16n8k16.row.col.f32.bf16.bf16.f32 "
        "{%0,%1,%2,%3}, {%4,%5,%6,%7}, {%8,%9}, {%0,%1,%2,%3};"
        : "+f"(c[0]), "+f"(c[1]), "+f"(c[2]), "+f"(c[3])
        : "r"(a[0]), "r"(a[1]), "r"(a[2]), "r"(a[3]), "r"(b[0]), "r"(b[1]));
}

// smem geometry for k_gmm
#define MATB     9216          // one 64x72 bf16 matrix (rows padded to 144B)
#define BUFB     36864         // Ah|Al|Bh|Bl
#define OFF_BS   73728
#define SMEM_GATES (OFF_BS + 256)

// ---------------- weight prep ----------------
__global__ void k_wt(const float* __restrict__ Kc){
    int idx = blockIdx.x*256 + threadIdx.x;
    int e = idx & 255, ct = idx >> 8;
    g_Kt[idx] = Kc[e*4608 + ct];
}
__global__ void k_wct2(const float* __restrict__ Wih, const float* __restrict__ Whh,
                       const float* __restrict__ bih, const float* __restrict__ bhh,
                       const float* __restrict__ Wch){
    int col = blockIdx.x;                       // 0..2303
    if (col < 2048){
        int j = col >> 2, g = col & 3;
        int row = g*512 + j;
        for (int k = threadIdx.x; k < KP2; k += 256){
            float v = 0.f;
            if (k < 512)        v = Whh[row*512 + k];
            else if (k < 1024)  v = Wih[row*517 + (k - 512)];
            else if (k < 1029)  v = Wih[row*517 + 512 + (k - 1024)];
            __nv_bfloat16 hi = __float2bfloat16_rn(v);
            g_Bhi[(size_t)col*KP2 + k] = hi;
            g_Blo[(size_t)col*KP2 + k] = __float2bfloat16_rn(v - __bfloat162float(hi));
        }
        if (threadIdx.x == 0) g_bsum[col] = bih[row] + bhh[row];
    } else {
        int e = col - 2048;
        for (int k = threadIdx.x; k < KP2; k += 256){
            float v = (k < 512) ? Wch[e*512 + k] : 0.f;
            __nv_bfloat16 hi = __float2bfloat16_rn(v);
            g_Bhi[(size_t)col*KP2 + k] = hi;
            g_Blo[(size_t)col*KP2 + k] = __float2bfloat16_rn(v - __bfloat162float(hi));
        }
    }
}

// ---------------- init hc ----------------
__global__ void k_init(const float* __restrict__ z, const float* __restrict__ W,
                       const float* __restrict__ bias){
    int b = blockIdx.x, tid = threadIdx.x;
    __shared__ float zs[128];
    if (tid < 128) zs[tid] = z[b*128 + tid];
    if (tid < 59){
        __nv_bfloat16 zb = __float2bfloat16_rn(0.f);
        g_Ahi[b*KP2 + KDIM + tid] = zb;
        g_Alo[b*KP2 + KDIM + tid] = zb;
    }
    __syncthreads();
    for (int j = tid; j < 1024; j += 256){
        const float4* wr = (const float4*)(W + j*128);
        const float4* zr = (const float4*)zs;
        float acc = bias[j];
        #pragma unroll 8
        for (int k = 0; k < 32; k++){
            float4 w = wr[k], zz = zr[k];
            acc += w.x*zz.x + w.y*zz.y + w.z*zz.z + w.w*zz.w;
        }
        float v = ftanh(acc);
        if (j < 512){
            __nv_bfloat16 hi = __float2bfloat16_rn(v);
            g_Ahi[b*KP2 + j] = hi;                       // h lives at K 0..511
            g_Alo[b*KP2 + j] = __float2bfloat16_rn(v - __bfloat162float(hi));
        } else g_c[b*512 + (j - 512)] = v;
    }
}

// ---------------- conv3x3 SAME -> g_xem[b][p][e] ----------------
__global__ void k_conv(const float* __restrict__ bbf, const float* __restrict__ bcf){
    int b = blockIdx.x, tid = threadIdx.x;
    int eg = tid >> 4, pg = tid & 15;
    __shared__ float in_s[4][64];
    __shared__ float w_s[4*9*256];
    float acc[4][16];
    #pragma unroll
    for (int i = 0; i < 4; i++)
        #pragma unroll
        for (int q = 0; q < 16; q++) acc[i][q] = 0.f;
    const float* src = bbf + b*CFEAT*HWSZ;
    for (int c0 = 0; c0 < CFEAT; c0 += 4){
        __syncthreads();
        const float4* ws4 = (const float4*)(g_Kt + c0*9*256);
        float4* wd4 = (float4*)w_s;
        for (int i = tid; i < 2304; i += 256) wd4[i] = ws4[i];
        { int c = tid >> 6, p = tid & 63; in_s[c][p] = src[(c0+c)*64 + p]; }
        __syncthreads();
        #pragma unroll
        for (int c = 0; c < 4; c++){
            #pragma unroll
            for (int tap = 0; tap < 9; tap++){
                int dy = tap/3 - 1, dx = tap%3 - 1;
                float xv[4];
                #pragma unroll
                for (int pp = 0; pp < 4; pp++){
                    int p = pg*4 + pp;
                    int py = (p >> 3) + dy, px = (p & 7) + dx;
                    xv[pp] = (py >= 0 && py < 8 && px >= 0 && px < 8)
                             ? in_s[c][py*8 + px] : 0.f;
                }
                const float4* wv4 = (const float4*)(w_s + (c*9+tap)*256 + eg*16);
                #pragma unroll
                for (int q = 0; q < 4; q++){
                    float4 w = wv4[q];
                    #pragma unroll
                    for (int pp = 0; pp < 4; pp++){
                        acc[pp][q*4+0] += xv[pp]*w.x;
                        acc[pp][q*4+1] += xv[pp]*w.y;
                        acc[pp][q*4+2] += xv[pp]*w.z;
                        acc[pp][q*4+3] += xv[pp]*w.w;
                    }
                }
            }
        }
    }
    #pragma unroll
    for (int pp = 0; pp < 4; pp++){
        int p = pg*4 + pp;
        float4* dst = (float4*)(g_xem + (b*HWSZ + p)*EMBD + eg*16);
        #pragma unroll
        for (int q = 0; q < 4; q++)
            dst[q] = make_float4(acc[pp][q*4+0]+bcf[eg*16+q*4+0],
                                 acc[pp][q*4+1]+bcf[eg*16+q*4+1],
                                 acc[pp][q*4+2]+bcf[eg*16+q*4+2],
                                 acc[pp][q*4+3]+bcf[eg*16+q*4+3]);
    }
}

// ---------------- attention (reads g_gem; no Wch GEMV) ----------------
__global__ void k_attn2(int t,
                        const float* __restrict__ Watt, const float* __restrict__ batt,
                        const float* __restrict__ bbf, const float* __restrict__ sketch){
    int b0 = blockIdx.x * 2, tid = threadIdx.x;
    __shared__ float g_s[2][256];
    __shared__ float sc[2][64];

    #pragma unroll
    for (int i = 0; i < 2; i++){
        int idx = tid + i*256;
        int bb = idx >> 8, e = idx & 255;
        g_s[bb][e] = g_gem[(b0+bb)*EMBD + e];
    }
    __syncthreads();
    {
        int pair = tid >> 1, half = tid & 1;
        int bb = pair >> 6, p = pair & 63;
        const float4* xr = (const float4*)(g_xem + ((b0+bb)*HWSZ + p)*EMBD + half*128);
        const float4* wa = (const float4*)(Watt + half*128);
        const float4* gv4 = (const float4*)(g_s[bb] + half*128);
        float acc = 0.f;
        #pragma unroll 4
        for (int k = 0; k < 32; k++){
            float4 xe = xr[k], w = wa[k], gv = gv4[k];
            acc += ftanh(xe.x+gv.x)*w.x + ftanh(xe.y+gv.y)*w.y
                 + ftanh(xe.z+gv.z)*w.z + ftanh(xe.w+gv.w)*w.w;
        }
        acc += __shfl_xor_sync(0xffffffffu, acc, 1);
        if (half == 0) sc[bb][p] = acc + batt[0];
    }
    __syncthreads();
    if (tid < 64){
        int bb = tid >> 5, lane = tid & 31;
        float v0 = sc[bb][lane], v1 = sc[bb][lane+32];
        float m = fmaxf(v0, v1);
        #pragma unroll
        for (int o = 16; o; o >>= 1) m = fmaxf(m, __shfl_xor_sync(0xffffffffu, m, o));
        float e0 = __expf(v0 - m), e1 = __expf(v1 - m);
        float s = e0 + e1;
        #pragma unroll
        for (int o = 16; o; o >>= 1) s += __shfl_xor_sync(0xffffffffu, s, o);
        float inv = __fdividef(1.f, s);
        sc[bb][lane] = e0*inv; sc[bb][lane+32] = e1*inv;
    }
    __syncthreads();
    #pragma unroll
    for (int bb = 0; bb < 2; bb++){
        #pragma unroll
        for (int cc = 0; cc < 2; cc++){
            int ch = tid + cc*256;
            const float4* fr = (const float4*)(bbf + ((b0+bb)*CFEAT + ch)*HWSZ);
            float acc = 0.f;
            #pragma unroll
            for (int k = 0; k < 16; k++){
                float4 f = fr[k];
                acc += sc[bb][k*4+0]*f.x + sc[bb][k*4+1]*f.y
                     + sc[bb][k*4+2]*f.z + sc[bb][k*4+3]*f.w;
            }
            __nv_bfloat16 hi = __float2bfloat16_rn(acc);
            g_Ahi[(b0+bb)*KP2 + 512 + ch] = hi;          // att at K 512..1023
            g_Alo[(b0+bb)*KP2 + 512 + ch] = __float2bfloat16_rn(acc - __bfloat162float(hi));
        }
    }
    if (tid < 10){
        int bb = tid / 5, d = tid % 5;
        float v = (t == 0) ? ((d == 2) ? 1.f : 0.f)
                           : sketch[((t-1)*BATCH + (b0+bb))*5 + d];
        __nv_bfloat16 hi = __float2bfloat16_rn(v);
        g_Ahi[(b0+bb)*KP2 + 1024 + d] = hi;              // pt at K 1024..1028
        g_Alo[(b0+bb)*KP2 + 1024 + d] = __float2bfloat16_rn(v - __bfloat162float(hi));
    }
}

// ---------------- staging: one 64-K chunk of Ah/Al/Bh/Bl into smem ----------
__device__ __forceinline__ void stage_chunk(uint32_t sb, int buf, int kc,
                                            int mb, int nb, int tid){
    const __nv_bfloat16* bases[4];
    bases[0] = g_Ahi + (size_t)mb*64*KP2;
    bases[1] = g_Alo + (size_t)mb*64*KP2;
    bases[2] = g_Bhi + (size_t)nb*64*KP2;
    bases[3] = g_Blo + (size_t)nb*64*KP2;
    uint32_t dbase = sb + buf*BUFB;
    #pragma unroll
    for (int mat = 0; mat < 4; mat++){
        const __nv_bfloat16* src0 = bases[mat] + kc*64;
        #pragma unroll
        for (int i = 0; i < 2; i++){
            int idx = tid + i*256;
            int r = idx >> 3, q = idx & 7;
            const __nv_bfloat16* src = src0 + (size_t)r*KP2 + q*8;
            uint32_t dst = dbase + mat*MATB + r*144 + q*16;
            CP_ASYNC16(dst, src);
        }
    }
}

// ---------------- generic split-bf16 HMMA GEMM -------------------------
// mode 0 (h-phase): K 0..511, nb 0..35 -> nb<32: g_part, nb>=32: g_gem+bch
// mode 2 (x-phase): K 512..1087, nb 0..31 -> + g_part + bsum -> LSTM epilogue
__global__ void __launch_bounds__(256)
k_gmm(int mode, int kclo, int nkc, int t, const float* __restrict__ bch){
    extern __shared__ char sm[];
    int tid = threadIdx.x;
    int wid = tid >> 5, lane = tid & 31;
    int mb = blockIdx.x;
    int nb = blockIdx.y;
    uint32_t sb = smem_u32(sm);

    float* bs = (float*)(sm + OFF_BS);
    if (mode == 2){ if (tid < 64) bs[tid] = g_bsum[nb*64 + tid]; }
    else if (nb >= 32){ if (tid < 64) bs[tid] = bch[(nb-32)*64 + tid]; }

    int wm = wid & 1, wn = wid >> 1;
    float acc[2][2][4];
    #pragma unroll
    for (int mi = 0; mi < 2; mi++)
        #pragma unroll
        for (int ni = 0; ni < 2; ni++)
            #pragma unroll
            for (int q = 0; q < 4; q++) acc[mi][ni][q] = 0.f;

    uint32_t aRow = (uint32_t)(wm*32 + (lane & 15));
    uint32_t aCol = (uint32_t)((lane >> 4) * 8);
    uint32_t bRow = (uint32_t)(wn*16 + (lane & 7));
    uint32_t bCol = (uint32_t)(((lane >> 3) & 1) * 8);

    stage_chunk(sb, 0, kclo, mb, nb, tid);
    CP_COMMIT();

    for (int i = 0; i < nkc; i++){
        int buf = i & 1;
        if (i + 1 < nkc){
            stage_chunk(sb, buf ^ 1, kclo + i + 1, mb, nb, tid);
            CP_COMMIT();
            CP_WAIT(1);
        } else {
            CP_WAIT(0);
        }
        __syncthreads();

        uint32_t base = sb + buf*BUFB;
        #pragma unroll
        for (int ks = 0; ks < 4; ks++){
            uint32_t kb = (uint32_t)(ks*32);
            uint32_t ah[2][4], al[2][4], bh[2][2], bl[2][2];
            #pragma unroll
            for (int mi = 0; mi < 2; mi++){
                uint32_t ao = (aRow + mi*16)*144 + kb + aCol*2;
                ldm_x4(ah[mi], base + ao);
                ldm_x4(al[mi], base + MATB + ao);
            }
            #pragma unroll
            for (int ni = 0; ni < 2; ni++){
                uint32_t bo = (bRow + ni*8)*144 + kb + bCol*2;
                ldm_x2(bh[ni], base + 2*MATB + bo);
                ldm_x2(bl[ni], base + 3*MATB + bo);
            }
            #pragma unroll
            for (int mi = 0; mi < 2; mi++)
                #pragma unroll
                for (int ni = 0; ni < 2; ni++){
                    mma_bf16(acc[mi][ni], ah[mi], bh[ni]);
                    mma_bf16(acc[mi][ni], ah[mi], bl[ni]);
                    mma_bf16(acc[mi][ni], al[mi], bh[ni]);
                }
        }
        __syncthreads();
    }

    // ---- epilogue: acc -> smem ----
    float* Cs = (float*)sm;
    #pragma unroll
    for (int mi = 0; mi < 2; mi++)
        #pragma unroll
        for (int ni = 0; ni < 2; ni++){
            int r0 = wm*32 + mi*16 + (lane >> 2);
            int c0 = wn*16 + ni*8 + (lane & 3)*2;
            Cs[r0*68 + c0]         = acc[mi][ni][0];
            Cs[r0*68 + c0 + 1]     = acc[mi][ni][1];
            Cs[(r0+8)*68 + c0]     = acc[mi][ni][2];
            Cs[(r0+8)*68 + c0 + 1] = acc[mi][ni][3];
        }
    __syncthreads();

    if (mode == 0){
        if (nb < 32){
            #pragma unroll
            for (int i = 0; i < 4; i++){
                int idx = tid + i*256;
                int bl_ = idx >> 4, jl = idx & 15;
                int b = mb*64 + bl_;
                *(float4*)&g_part[b*2048 + nb*64 + jl*4] = *(const float4*)&Cs[bl_*68 + jl*4];
            }
        } else {
            #pragma unroll
            for (int i = 0; i < 4; i++){
                int idx = tid + i*256;
                int bl_ = idx >> 4, jl = idx & 15;
                int b = mb*64 + bl_;
                float4 g4 = *(const float4*)&Cs[bl_*68 + jl*4];
                float4 b4 = *(const float4*)&bs[jl*4];
                *(float4*)&g_gem[b*EMBD + (nb-32)*64 + jl*4] =
                    make_float4(g4.x+b4.x, g4.y+b4.y, g4.z+b4.z, g4.w+b4.w);
            }
        }
    } else {
        #pragma unroll
        for (int i = 0; i < 4; i++){
            int idx = tid + i*256;
            int bl_ = idx >> 4, jl = idx & 15;
            int b = mb*64 + bl_;
            int j = nb*16 + jl;
            float4 g4 = *(const float4*)&Cs[bl_*68 + jl*4];
            float4 p4 = *(const float4*)&g_part[b*2048 + nb*64 + jl*4];
            float4 b4 = *(const float4*)&bs[jl*4];
            float iv = fsig (g4.x + p4.x + b4.x);
            float fv = fsig (g4.y + p4.y + b4.y);
            float gv = ftanh(g4.z + p4.z + b4.z);
            float ov = fsig (g4.w + p4.w + b4.w);
            float cold = g_c[b*512 + j];
            float cnew = fv*cold + iv*gv;
            float hnew = ov*ftanh(cnew);
            g_c[b*512 + j] = cnew;
            g_hid[(t*BATCH + b)*512 + j] = hnew;
            __nv_bfloat16 hi = __float2bfloat16_rn(hnew);
            g_Ahi[b*KP2 + j] = hi;                       // h at K 0..511
            g_Alo[b*KP2 + j] = __float2bfloat16_rn(hnew - __bfloat162float(hi));
        }
    }
}

// ---------------- final projection ----------------
__global__ void k_proj(const float* __restrict__ Wfc){
    int n0 = blockIdx.x * 64;
    int tid = threadIdx.x;
    int jg = tid & 31, rg = tid >> 5;
    __shared__ float h_s[32][68];
    __shared__ float w_s[32][132];
    float acc[8][4];
    #pragma unroll
    for (int r = 0; r < 8; r++)
        #pragma unroll
        for (int q = 0; q < 4; q++) acc[r][q] = 0.f;
    for (int k0 = 0; k0 < 512; k0 += 32){
        __syncthreads();
        #pragma unroll
        for (int i = 0; i < 8; i++){
            int li = tid + 256*i;
            int r = li >> 5, kk = li & 31;
            int n = n0 + r;
            int b = n / 257, tt = n - b*257;
            h_s[kk][r] = g_hid[(tt*BATCH + b)*512 + k0 + kk];
        }
        #pragma unroll
        for (int i = 0; i < 16; i++){
            int li = tid + 256*i;
            int jrow = li >> 5, kk = li & 31;
            w_s[kk][jrow] = (jrow < 123) ? Wfc[jrow*512 + k0 + kk] : 0.f;
        }
        __syncthreads();
        #pragma unroll
        for (int k = 0; k < 32; k++){
            float4 wv = *(const float4*)&w_s[k][jg*4];
            float4 h0 = *(const float4*)&h_s[k][rg*8];
            float4 h1 = *(const float4*)&h_s[k][rg*8 + 4];
            float hq[8] = {h0.x,h0.y,h0.z,h0.w,h1.x,h1.y,h1.z,h1.w};
            float wq[4] = {wv.x,wv.y,wv.z,wv.w};
            #pragma unroll
            for (int r = 0; r < 8; r++)
                #pragma unroll
                for (int q = 0; q < 4; q++)
                    acc[r][q] += hq[r]*wq[q];
        }
    }
    #pragma unroll
    for (int r = 0; r < 8; r++){
        int n = n0 + rg*8 + r;
        #pragma unroll
        for (int q = 0; q < 4; q++){
            int jc = jg*4 + q;
            if (jc < 123) g_y[n*128 + jc] = acc[r][q];
        }
    }
}

// ---------------- output transforms ----------------
__global__ void k_out(float* __restrict__ out, const float* __restrict__ bfc){
    int n = blockIdx.x*8 + (threadIdx.x >> 5);
    int lane = threadIdx.x & 31;
    const float* y = g_y + n*128;
    const int N = NROWS;
    float pi = (lane < 20) ? (y[3+lane] + bfc[3+lane]) : -3.4e38f;
    float m = pi;
    #pragma unroll
    for (int o = 16; o; o >>= 1) m = fmaxf(m, __shfl_xor_sync(0xffffffffu, m, o));
    float e = (lane < 20) ? __expf(pi - m) : 0.f;
    float s = e;
    #pragma unroll
    for (int o = 16; o; o >>= 1) s += __shfl_xor_sync(0xffffffffu, s, o);
    float inv = __fdividef(1.f, s);
    if (lane < 20){
        out[           n*20 + lane] = e*inv;
        out[  N*20   + n*20 + lane] = y[23 + lane] + bfc[23 + lane];
        out[2*N*20   + n*20 + lane] = y[43 + lane] + bfc[43 + lane];
        out[3*N*20   + n*20 + lane] = __expf(y[63 + lane] + bfc[63 + lane]);
        out[4*N*20   + n*20 + lane] = __expf(y[83 + lane] + bfc[83 + lane]);
        out[5*N*20   + n*20 + lane] = ftanh(y[103 + lane] + bfc[103 + lane]);
    }
    if (lane < 3)
        out[6*N*20 + n*3 + lane] = y[lane] + bfc[lane];
}

extern "C" void kernel_launch(void* const* d_in, const int* in_sizes, int n_in,
                              void* d_out, int out_size){
    const float* bbf    = (const float*)d_in[0];
    const float* z      = (const float*)d_in[1];
    const float* sk     = (const float*)d_in[2];
    const float* Wfc_hc = (const float*)d_in[3];
    const float* bfc_hc = (const float*)d_in[4];
    const float* Wch    = (const float*)d_in[5];
    const float* bch    = (const float*)d_in[6];
    const float* Kcf    = (const float*)d_in[7];
    const float* bcf    = (const float*)d_in[8];
    const float* Watt   = (const float*)d_in[9];
    const float* batt   = (const float*)d_in[10];
    const float* Wih    = (const float*)d_in[11];
    const float* Whh    = (const float*)d_in[12];
    const float* bih    = (const float*)d_in[13];
    const float* bhh    = (const float*)d_in[14];
    const float* Wfcp   = (const float*)d_in[15];
    const float* bfcp   = (const float*)d_in[16];
    float* out = (float*)d_out;

    cudaFuncSetAttribute(k_gmm, cudaFuncAttributeMaxDynamicSharedMemorySize, SMEM_GATES);

    k_wt   <<<4608, 256>>>(Kcf);
    k_wct2 <<<NCOL, 256>>>(Wih, Whh, bih, bhh, Wch);
    k_init <<<256, 256>>>(z, Wfc_hc, bfc_hc);
    k_conv <<<256, 256>>>(bbf, bcf);

    for (int t = 0; t < NSTEP; t++){
        // h-part partial gates + g_em (both depend only on h(t))
        k_gmm<<<dim3(4, 36), 256, SMEM_GATES>>>(0, 0, 8, t, bch);
        // attention (needs g_gem, g_xem)
        k_attn2<<<128, 256>>>(t, Watt, batt, bbf, sk);
        // att-part gates + LSTM epilogue
        k_gmm<<<dim3(4, 32), 256, SMEM_GATES>>>(2, 8, 9, t, nullptr);
    }
    k_proj<<<1028, 256>>>(Wfcp);
    k_out <<<8224, 256>>>(out, bfcp);
}

// round 9
// speedup vs baseline: 2.3288x; 1.0645x over previous
#include <cuda_runtime.h>
#include <cuda_bf16.h>
#include <cstdint>

#define BATCH   256
#define HDIM    512
#define EMBD    256
#define CFEAT   512
#define HWSZ    64
#define NSTEP   257
#define KDIM    1029
#define KP2     1088        // K padded (17 * 64)
#define NCOL    2304        // 2048 gate cols + 256 g_em cols
#define NROWS   (BATCH*NSTEP)

// ---------------- device scratch ----------------
__device__ float g_c[BATCH*HDIM];
__device__ float g_xem[BATCH*HWSZ*EMBD];
__device__ float g_y[NROWS*128];
__device__ float g_part[BATCH*2048];            // partial gates (h-part)
__device__ float g_gem[BATCH*EMBD];             // g_em + bias
__device__ __nv_bfloat16 g_Ahi[BATCH*KP2];      // A rows [h|att|pt|pad]
__device__ __nv_bfloat16 g_Alo[BATCH*KP2];
__device__ __nv_bfloat16 g_Bhi[(size_t)NCOL*KP2];
__device__ __nv_bfloat16 g_Blo[(size_t)NCOL*KP2];
__device__ float g_bsum[2048];
// conv-GEMM operands
__device__ __nv_bfloat16 g_Phi[BATCH*100*512];  // padded patches [b*100+pos][c]
__device__ __nv_bfloat16 g_Plo[BATCH*100*512];
__device__ __nv_bfloat16 g_Chi[9*256*512];      // tap weights [tap][e][c]
__device__ __nv_bfloat16 g_Clo[9*256*512];
// projection operands
__device__ __nv_bfloat16 g_Hhi[(size_t)NSTEP*BATCH*HDIM];
__device__ __nv_bfloat16 g_Hlo[(size_t)NSTEP*BATCH*HDIM];
__device__ __nv_bfloat16 g_Wfhi[128*512];
__device__ __nv_bfloat16 g_Wflo[128*512];

// ---------------- math helpers ----------------
__device__ __forceinline__ float ftanh(float x){
    float x2 = x*x;
    float p = x*(135135.f + x2*(17325.f + x2*(378.f + x2)));
    float q = 135135.f + x2*(62370.f + x2*(3150.f + x2*28.f));
    float r = __int_as_float(0x7EF311C3u - __float_as_int(q));
    r = r*(2.f - q*r);
    r = r*(2.f - q*r);
    r = r*(2.f - q*r);
    float t = p*r;
    return fmaxf(-1.f, fminf(1.f, t));
}
__device__ __forceinline__ float fsig(float x){
    return 0.5f + 0.5f*ftanh(0.5f*x);
}
__device__ __forceinline__ float fatanh(float x){   // HW MUFU.TANH (attention only)
    float y;
    asm("tanh.approx.f32 %0, %1;" : "=f"(y) : "f"(x));
    return y;
}

// ---------------- PTX helpers ----------------
__device__ __forceinline__ uint32_t smem_u32(const void* p){
    uint32_t a;
    asm("{ .reg .u64 t; cvta.to.shared.u64 t, %1; cvt.u32.u64 %0, t; }" : "=r"(a) : "l"(p));
    return a;
}
#define CP_ASYNC16(dst, src) \
    asm volatile("cp.async.cg.shared.global [%0], [%1], 16;" :: "r"(dst), "l"(src))
#define CP_COMMIT()  asm volatile("cp.async.commit_group;" ::: "memory")
#define CP_WAIT(n)   asm volatile("cp.async.wait_group %0;" :: "n"(n) : "memory")

__device__ __forceinline__ void ldm_x4(uint32_t* r, uint32_t addr){
    asm volatile("ldmatrix.sync.aligned.m8n8.x4.shared.b16 {%0,%1,%2,%3}, [%4];"
        : "=r"(r[0]), "=r"(r[1]), "=r"(r[2]), "=r"(r[3]) : "r"(addr));
}
__device__ __forceinline__ void ldm_x2(uint32_t* r, uint32_t addr){
    asm volatile("ldmatrix.sync.aligned.m8n8.x2.shared.b16 {%0,%1}, [%2];"
        : "=r"(r[0]), "=r"(r[1]) : "r"(addr));
}
__device__ __forceinline__ void mma_bf16(float* c, const uint32_t* a, const uint32_t* b){
    asm volatile("mma.sync.aligned.m16n8k16.row.col.f32.bf16.bf16.f32 "
        "{%0,%1,%2,%3}, {%4,%5,%6,%7}, {%8,%9}, {%0,%1,%2,%3};"
        : "+f"(c[0]), "+f"(c[1]), "+f"(c[2]), "+f"(c[3])
        : "r"(a[0]), "r"(a[1]), "r"(a[2]), "r"(a[3]), "r"(b[0]), "r"(b[1]));
}

// smem geometry for GEMM kernels
#define MATB     9216          // one 64x72 bf16 matrix (rows padded to 144B)
#define BUFB     36864         // Ah|Al|Bh|Bl
#define OFF_BS   73728
#define SMEM_GATES (OFF_BS + 256)

// ---------------- weight prep ----------------
__global__ void k_wct2(const float* __restrict__ Wih, const float* __restrict__ Whh,
                       const float* __restrict__ bih, const float* __restrict__ bhh,
                       const float* __restrict__ Wch){
    int col = blockIdx.x;                       // 0..2303
    if (col < 2048){
        int j = col >> 2, g = col & 3;
        int row = g*512 + j;
        for (int k = threadIdx.x; k < KP2; k += 256){
            float v = 0.f;
            if (k < 512)        v = Whh[row*512 + k];
            else if (k < 1024)  v = Wih[row*517 + (k - 512)];
            else if (k < 1029)  v = Wih[row*517 + 512 + (k - 1024)];
            __nv_bfloat16 hi = __float2bfloat16_rn(v);
            g_Bhi[(size_t)col*KP2 + k] = hi;
            g_Blo[(size_t)col*KP2 + k] = __float2bfloat16_rn(v - __bfloat162float(hi));
        }
        if (threadIdx.x == 0) g_bsum[col] = bih[row] + bhh[row];
    } else {
        int e = col - 2048;
        for (int k = threadIdx.x; k < KP2; k += 256){
            float v = (k < 512) ? Wch[e*512 + k] : 0.f;
            __nv_bfloat16 hi = __float2bfloat16_rn(v);
            g_Bhi[(size_t)col*KP2 + k] = hi;
            g_Blo[(size_t)col*KP2 + k] = __float2bfloat16_rn(v - __bfloat162float(hi));
        }
    }
}
// conv tap weights: g_Chi[tap][e][c] = Kcf[e][c*9 + tap]
__global__ void k_wc(const float* __restrict__ Kcf){
    int idx = blockIdx.x*256 + threadIdx.x;     // 9*256*512 = 1179648
    int c = idx & 511, r = idx >> 9;
    int e = r & 255, tap = r >> 8;
    float v = Kcf[e*4608 + c*9 + tap];
    __nv_bfloat16 hi = __float2bfloat16_rn(v);
    g_Chi[idx] = hi;
    g_Clo[idx] = __float2bfloat16_rn(v - __bfloat162float(hi));
}
// padded patches: g_Phi[b*100 + pos][c], pos = (py+1)*10 + (px+1)
__global__ void k_im2(const float* __restrict__ bbf){
    int b = blockIdx.x;
    for (int idx = threadIdx.x; idx < 100*512; idx += 256){
        int pos = idx >> 9, c = idx & 511;
        int py = pos/10 - 1, px = pos%10 - 1;
        float v = 0.f;
        if (py >= 0 && py < 8 && px >= 0 && px < 8)
            v = bbf[(b*512 + c)*64 + py*8 + px];
        __nv_bfloat16 hi = __float2bfloat16_rn(v);
        g_Phi[b*51200 + idx] = hi;
        g_Plo[b*51200 + idx] = __float2bfloat16_rn(v - __bfloat162float(hi));
    }
}
// projection weights: g_Wfhi[col][k], col<123 real
__global__ void k_wfc(const float* __restrict__ Wfc){
    int col = blockIdx.x;                       // 0..127
    for (int k = threadIdx.x; k < 512; k += 256){
        float v = (col < 123) ? Wfc[col*512 + k] : 0.f;
        __nv_bfloat16 hi = __float2bfloat16_rn(v);
        g_Wfhi[col*512 + k] = hi;
        g_Wflo[col*512 + k] = __float2bfloat16_rn(v - __bfloat162float(hi));
    }
}

// ---------------- init hc ----------------
__global__ void k_init(const float* __restrict__ z, const float* __restrict__ W,
                       const float* __restrict__ bias){
    int b = blockIdx.x, tid = threadIdx.x;
    __shared__ float zs[128];
    if (tid < 128) zs[tid] = z[b*128 + tid];
    if (tid < 59){
        __nv_bfloat16 zb = __float2bfloat16_rn(0.f);
        g_Ahi[b*KP2 + KDIM + tid] = zb;
        g_Alo[b*KP2 + KDIM + tid] = zb;
    }
    __syncthreads();
    for (int j = tid; j < 1024; j += 256){
        const float4* wr = (const float4*)(W + j*128);
        const float4* zr = (const float4*)zs;
        float acc = bias[j];
        #pragma unroll 8
        for (int k = 0; k < 32; k++){
            float4 w = wr[k], zz = zr[k];
            acc += w.x*zz.x + w.y*zz.y + w.z*zz.z + w.w*zz.w;
        }
        float v = ftanh(acc);
        if (j < 512){
            __nv_bfloat16 hi = __float2bfloat16_rn(v);
            g_Ahi[b*KP2 + j] = hi;
            g_Alo[b*KP2 + j] = __float2bfloat16_rn(v - __bfloat162float(hi));
        } else g_c[b*512 + (j - 512)] = v;
    }
}

// ---------------- conv as 9-tap accumulated HMMA GEMM ----------------
// out[b*64+p][e] = sum_tap sum_c P[b*100 + base(p)+toff(tap)][c] * C[tap][e][c]
__device__ __forceinline__ void stage_conv(uint32_t sb, int buf, int cc,
                                           int mb, int nb, int tid){
    int tap = cc >> 3, kc = cc & 7;
    int toff = (tap/3)*10 + (tap%3);
    uint32_t dbase = sb + buf*BUFB;
    #pragma unroll
    for (int i = 0; i < 2; i++){
        int idx = tid + i*256;
        int r = idx >> 3, q = idx & 7;
        int arow = mb*100 + (r >> 3)*10 + (r & 7) + toff;
        size_t so = (size_t)arow*512 + kc*64 + q*8;
        uint32_t dst = dbase + r*144 + q*16;
        CP_ASYNC16(dst,        g_Phi + so);
        CP_ASYNC16(dst + MATB, g_Plo + so);
        int brow = tap*256 + nb*64 + r;
        size_t bo = (size_t)brow*512 + kc*64 + q*8;
        CP_ASYNC16(dst + 2*MATB, g_Chi + bo);
        CP_ASYNC16(dst + 3*MATB, g_Clo + bo);
    }
}
__global__ void __launch_bounds__(256)
k_cgmm(const float* __restrict__ bcf){
    extern __shared__ char sm[];
    int tid = threadIdx.x;
    int wid = tid >> 5, lane = tid & 31;
    int mb = blockIdx.x;                    // batch (64 positions)
    int nb = blockIdx.y;                    // 64 e-cols
    uint32_t sb = smem_u32(sm);
    float* bs = (float*)(sm + OFF_BS);
    if (tid < 64) bs[tid] = bcf[nb*64 + tid];

    int wm = wid & 1, wn = wid >> 1;
    float acc[2][2][4];
    #pragma unroll
    for (int mi = 0; mi < 2; mi++)
        #pragma unroll
        for (int ni = 0; ni < 2; ni++)
            #pragma unroll
            for (int q = 0; q < 4; q++) acc[mi][ni][q] = 0.f;

    uint32_t aRow = (uint32_t)(wm*32 + (lane & 15));
    uint32_t aCol = (uint32_t)((lane >> 4) * 8);
    uint32_t bRow = (uint32_t)(wn*16 + (lane & 7));
    uint32_t bCol = (uint32_t)(((lane >> 3) & 1) * 8);

    stage_conv(sb, 0, 0, mb, nb, tid);
    CP_COMMIT();
    for (int cc = 0; cc < 72; cc++){
        int buf = cc & 1;
        if (cc + 1 < 72){
            stage_conv(sb, buf ^ 1, cc + 1, mb, nb, tid);
            CP_COMMIT();
            CP_WAIT(1);
        } else CP_WAIT(0);
        __syncthreads();
        uint32_t base = sb + buf*BUFB;
        #pragma unroll
        for (int ks = 0; ks < 4; ks++){
            uint32_t kb = (uint32_t)(ks*32);
            uint32_t ah[2][4], al[2][4], bh[2][2], bl[2][2];
            #pragma unroll
            for (int mi = 0; mi < 2; mi++){
                uint32_t ao = (aRow + mi*16)*144 + kb + aCol*2;
                ldm_x4(ah[mi], base + ao);
                ldm_x4(al[mi], base + MATB + ao);
            }
            #pragma unroll
            for (int ni = 0; ni < 2; ni++){
                uint32_t bo = (bRow + ni*8)*144 + kb + bCol*2;
                ldm_x2(bh[ni], base + 2*MATB + bo);
                ldm_x2(bl[ni], base + 3*MATB + bo);
            }
            #pragma unroll
            for (int mi = 0; mi < 2; mi++)
                #pragma unroll
                for (int ni = 0; ni < 2; ni++){
                    mma_bf16(acc[mi][ni], ah[mi], bh[ni]);
                    mma_bf16(acc[mi][ni], ah[mi], bl[ni]);
                    mma_bf16(acc[mi][ni], al[mi], bh[ni]);
                }
        }
        __syncthreads();
    }
    float* Cs = (float*)sm;
    #pragma unroll
    for (int mi = 0; mi < 2; mi++)
        #pragma unroll
        for (int ni = 0; ni < 2; ni++){
            int r0 = wm*32 + mi*16 + (lane >> 2);
            int c0 = wn*16 + ni*8 + (lane & 3)*2;
            Cs[r0*68 + c0]         = acc[mi][ni][0];
            Cs[r0*68 + c0 + 1]     = acc[mi][ni][1];
            Cs[(r0+8)*68 + c0]     = acc[mi][ni][2];
            Cs[(r0+8)*68 + c0 + 1] = acc[mi][ni][3];
        }
    __syncthreads();
    #pragma unroll
    for (int i = 0; i < 4; i++){
        int idx = tid + i*256;
        int r = idx >> 4, jl = idx & 15;
        float4 g4 = *(const float4*)&Cs[r*68 + jl*4];
        float4 b4 = *(const float4*)&bs[jl*4];
        *(float4*)&g_xem[(mb*64 + r)*256 + nb*64 + jl*4] =
            make_float4(g4.x+b4.x, g4.y+b4.y, g4.z+b4.z, g4.w+b4.w);
    }
}

// ---------------- attention ----------------
__global__ void k_attn2(int t,
                        const float* __restrict__ Watt, const float* __restrict__ batt,
                        const float* __restrict__ bbf, const float* __restrict__ sketch){
    int b0 = blockIdx.x * 2, tid = threadIdx.x;
    __shared__ float g_s[2][256];
    __shared__ float sc[2][64];

    #pragma unroll
    for (int i = 0; i < 2; i++){
        int idx = tid + i*256;
        int bb = idx >> 8, e = idx & 255;
        g_s[bb][e] = g_gem[(b0+bb)*EMBD + e];
    }
    __syncthreads();
    {
        int pair = tid >> 1, half = tid & 1;
        int bb = pair >> 6, p = pair & 63;
        const float4* xr = (const float4*)(g_xem + ((b0+bb)*HWSZ + p)*EMBD + half*128);
        const float4* wa = (const float4*)(Watt + half*128);
        const float4* gv4 = (const float4*)(g_s[bb] + half*128);
        float acc = 0.f;
        #pragma unroll 4
        for (int k = 0; k < 32; k++){
            float4 xe = xr[k], w = wa[k], gv = gv4[k];
            acc += fatanh(xe.x+gv.x)*w.x + fatanh(xe.y+gv.y)*w.y
                 + fatanh(xe.z+gv.z)*w.z + fatanh(xe.w+gv.w)*w.w;
        }
        acc += __shfl_xor_sync(0xffffffffu, acc, 1);
        if (half == 0) sc[bb][p] = acc + batt[0];
    }
    __syncthreads();
    if (tid < 64){
        int bb = tid >> 5, lane = tid & 31;
        float v0 = sc[bb][lane], v1 = sc[bb][lane+32];
        float m = fmaxf(v0, v1);
        #pragma unroll
        for (int o = 16; o; o >>= 1) m = fmaxf(m, __shfl_xor_sync(0xffffffffu, m, o));
        float e0 = __expf(v0 - m), e1 = __expf(v1 - m);
        float s = e0 + e1;
        #pragma unroll
        for (int o = 16; o; o >>= 1) s += __shfl_xor_sync(0xffffffffu, s, o);
        float inv = __fdividef(1.f, s);
        sc[bb][lane] = e0*inv; sc[bb][lane+32] = e1*inv;
    }
    __syncthreads();
    #pragma unroll
    for (int bb = 0; bb < 2; bb++){
        #pragma unroll
        for (int cc = 0; cc < 2; cc++){
            int ch = tid + cc*256;
            const float4* fr = (const float4*)(bbf + ((b0+bb)*CFEAT + ch)*HWSZ);
            float acc = 0.f;
            #pragma unroll
            for (int k = 0; k < 16; k++){
                float4 f = fr[k];
                acc += sc[bb][k*4+0]*f.x + sc[bb][k*4+1]*f.y
                     + sc[bb][k*4+2]*f.z + sc[bb][k*4+3]*f.w;
            }
            __nv_bfloat16 hi = __float2bfloat16_rn(acc);
            g_Ahi[(b0+bb)*KP2 + 512 + ch] = hi;
            g_Alo[(b0+bb)*KP2 + 512 + ch] = __float2bfloat16_rn(acc - __bfloat162float(hi));
        }
    }
    if (tid < 10){
        int bb = tid / 5, d = tid % 5;
        float v = (t == 0) ? ((d == 2) ? 1.f : 0.f)
                           : sketch[((t-1)*BATCH + (b0+bb))*5 + d];
        __nv_bfloat16 hi = __float2bfloat16_rn(v);
        g_Ahi[(b0+bb)*KP2 + 1024 + d] = hi;
        g_Alo[(b0+bb)*KP2 + 1024 + d] = __float2bfloat16_rn(v - __bfloat162float(hi));
    }
}

// ---------------- gates GEMM staging ----------------
__device__ __forceinline__ void stage_chunk(uint32_t sb, int buf, int kc,
                                            int mb, int nb, int tid){
    uint32_t dbase = sb + buf*BUFB;
    #pragma unroll
    for (int i = 0; i < 2; i++){
        int idx = tid + i*256;
        int r = idx >> 3, q = idx & 7;
        size_t so = (size_t)(mb*64 + r)*KP2 + kc*64 + q*8;
        uint32_t dst = dbase + r*144 + q*16;
        CP_ASYNC16(dst,        g_Ahi + so);
        CP_ASYNC16(dst + MATB, g_Alo + so);
        size_t bo = (size_t)(nb*64 + r)*KP2 + kc*64 + q*8;
        CP_ASYNC16(dst + 2*MATB, g_Bhi + bo);
        CP_ASYNC16(dst + 3*MATB, g_Blo + bo);
    }
}

// ---------------- gates split-bf16 HMMA GEMM ----------------
// mode 0 (h-phase): K 0..511, nb 0..35 -> nb<32: g_part, nb>=32: g_gem+bch
// mode 2 (x-phase): K 512..1087, nb 0..31 -> + g_part + bsum -> LSTM epilogue
__global__ void __launch_bounds__(256)
k_gmm(int mode, int kclo, int nkc, int t, const float* __restrict__ bch){
    extern __shared__ char sm[];
    int tid = threadIdx.x;
    int wid = tid >> 5, lane = tid & 31;
    int mb = blockIdx.x;
    int nb = blockIdx.y;
    uint32_t sb = smem_u32(sm);

    float* bs = (float*)(sm + OFF_BS);
    if (mode == 2){ if (tid < 64) bs[tid] = g_bsum[nb*64 + tid]; }
    else if (nb >= 32){ if (tid < 64) bs[tid] = bch[(nb-32)*64 + tid]; }

    int wm = wid & 1, wn = wid >> 1;
    float acc[2][2][4];
    #pragma unroll
    for (int mi = 0; mi < 2; mi++)
        #pragma unroll
        for (int ni = 0; ni < 2; ni++)
            #pragma unroll
            for (int q = 0; q < 4; q++) acc[mi][ni][q] = 0.f;

    uint32_t aRow = (uint32_t)(wm*32 + (lane & 15));
    uint32_t aCol = (uint32_t)((lane >> 4) * 8);
    uint32_t bRow = (uint32_t)(wn*16 + (lane & 7));
    uint32_t bCol = (uint32_t)(((lane >> 3) & 1) * 8);

    stage_chunk(sb, 0, kclo, mb, nb, tid);
    CP_COMMIT();
    for (int i = 0; i < nkc; i++){
        int buf = i & 1;
        if (i + 1 < nkc){
            stage_chunk(sb, buf ^ 1, kclo + i + 1, mb, nb, tid);
            CP_COMMIT();
            CP_WAIT(1);
        } else CP_WAIT(0);
        __syncthreads();
        uint32_t base = sb + buf*BUFB;
        #pragma unroll
        for (int ks = 0; ks < 4; ks++){
            uint32_t kb = (uint32_t)(ks*32);
            uint32_t ah[2][4], al[2][4], bh[2][2], bl[2][2];
            #pragma unroll
            for (int mi = 0; mi < 2; mi++){
                uint32_t ao = (aRow + mi*16)*144 + kb + aCol*2;
                ldm_x4(ah[mi], base + ao);
                ldm_x4(al[mi], base + MATB + ao);
            }
            #pragma unroll
            for (int ni = 0; ni < 2; ni++){
                uint32_t bo = (bRow + ni*8)*144 + kb + bCol*2;
                ldm_x2(bh[ni], base + 2*MATB + bo);
                ldm_x2(bl[ni], base + 3*MATB + bo);
            }
            #pragma unroll
            for (int mi = 0; mi < 2; mi++)
                #pragma unroll
                for (int ni = 0; ni < 2; ni++){
                    mma_bf16(acc[mi][ni], ah[mi], bh[ni]);
                    mma_bf16(acc[mi][ni], ah[mi], bl[ni]);
                    mma_bf16(acc[mi][ni], al[mi], bh[ni]);
                }
        }
        __syncthreads();
    }

    float* Cs = (float*)sm;
    #pragma unroll
    for (int mi = 0; mi < 2; mi++)
        #pragma unroll
        for (int ni = 0; ni < 2; ni++){
            int r0 = wm*32 + mi*16 + (lane >> 2);
            int c0 = wn*16 + ni*8 + (lane & 3)*2;
            Cs[r0*68 + c0]         = acc[mi][ni][0];
            Cs[r0*68 + c0 + 1]     = acc[mi][ni][1];
            Cs[(r0+8)*68 + c0]     = acc[mi][ni][2];
            Cs[(r0+8)*68 + c0 + 1] = acc[mi][ni][3];
        }
    __syncthreads();

    if (mode == 0){
        if (nb < 32){
            #pragma unroll
            for (int i = 0; i < 4; i++){
                int idx = tid + i*256;
                int bl_ = idx >> 4, jl = idx & 15;
                int b = mb*64 + bl_;
                *(float4*)&g_part[b*2048 + nb*64 + jl*4] = *(const float4*)&Cs[bl_*68 + jl*4];
            }
        } else {
            #pragma unroll
            for (int i = 0; i < 4; i++){
                int idx = tid + i*256;
                int bl_ = idx >> 4, jl = idx & 15;
                int b = mb*64 + bl_;
                float4 g4 = *(const float4*)&Cs[bl_*68 + jl*4];
                float4 b4 = *(const float4*)&bs[jl*4];
                *(float4*)&g_gem[b*EMBD + (nb-32)*64 + jl*4] =
                    make_float4(g4.x+b4.x, g4.y+b4.y, g4.z+b4.z, g4.w+b4.w);
            }
        }
    } else {
        #pragma unroll
        for (int i = 0; i < 4; i++){
            int idx = tid + i*256;
            int bl_ = idx >> 4, jl = idx & 15;
            int b = mb*64 + bl_;
            int j = nb*16 + jl;
            float4 g4 = *(const float4*)&Cs[bl_*68 + jl*4];
            float4 p4 = *(const float4*)&g_part[b*2048 + nb*64 + jl*4];
            float4 b4 = *(const float4*)&bs[jl*4];
            float iv = fsig (g4.x + p4.x + b4.x);
            float fv = fsig (g4.y + p4.y + b4.y);
            float gv = ftanh(g4.z + p4.z + b4.z);
            float ov = fsig (g4.w + p4.w + b4.w);
            float cold = g_c[b*512 + j];
            float cnew = fv*cold + iv*gv;
            float hnew = ov*ftanh(cnew);
            g_c[b*512 + j] = cnew;
            __nv_bfloat16 hi = __float2bfloat16_rn(hnew);
            __nv_bfloat16 lo = __float2bfloat16_rn(hnew - __bfloat162float(hi));
            g_Ahi[b*KP2 + j] = hi;
            g_Alo[b*KP2 + j] = lo;
            size_t hidx = (size_t)(t*BATCH + b)*512 + j;
            g_Hhi[hidx] = hi;
            g_Hlo[hidx] = lo;
        }
    }
}

// ---------------- projection GEMM: g_y[R][col] = H[R] . Wf[col] ----------
__device__ __forceinline__ void stage_proj(uint32_t sb, int buf, int kc,
                                           int mb, int nb, int tid){
    uint32_t dbase = sb + buf*BUFB;
    #pragma unroll
    for (int i = 0; i < 2; i++){
        int idx = tid + i*256;
        int r = idx >> 3, q = idx & 7;
        size_t so = (size_t)(mb*64 + r)*512 + kc*64 + q*8;
        uint32_t dst = dbase + r*144 + q*16;
        CP_ASYNC16(dst,        g_Hhi + so);
        CP_ASYNC16(dst + MATB, g_Hlo + so);
        size_t bo = (size_t)(nb*64 + r)*512 + kc*64 + q*8;
        CP_ASYNC16(dst + 2*MATB, g_Wfhi + bo);
        CP_ASYNC16(dst + 3*MATB, g_Wflo + bo);
    }
}
__global__ void __launch_bounds__(256)
k_pgmm(){
    extern __shared__ char sm[];
    int tid = threadIdx.x;
    int wid = tid >> 5, lane = tid & 31;
    int mb = blockIdx.x;                    // 0..1027
    int nb = blockIdx.y;                    // 0..1
    uint32_t sb = smem_u32(sm);

    int wm = wid & 1, wn = wid >> 1;
    float acc[2][2][4];
    #pragma unroll
    for (int mi = 0; mi < 2; mi++)
        #pragma unroll
        for (int ni = 0; ni < 2; ni++)
            #pragma unroll
            for (int q = 0; q < 4; q++) acc[mi][ni][q] = 0.f;

    uint32_t aRow = (uint32_t)(wm*32 + (lane & 15));
    uint32_t aCol = (uint32_t)((lane >> 4) * 8);
    uint32_t bRow = (uint32_t)(wn*16 + (lane & 7));
    uint32_t bCol = (uint32_t)(((lane >> 3) & 1) * 8);

    stage_proj(sb, 0, 0, mb, nb, tid);
    CP_COMMIT();
    for (int i = 0; i < 8; i++){
        int buf = i & 1;
        if (i + 1 < 8){
            stage_proj(sb, buf ^ 1, i + 1, mb, nb, tid);
            CP_COMMIT();
            CP_WAIT(1);
        } else CP_WAIT(0);
        __syncthreads();
        uint32_t base = sb + buf*BUFB;
        #pragma unroll
        for (int ks = 0; ks < 4; ks++){
            uint32_t kb = (uint32_t)(ks*32);
            uint32_t ah[2][4], al[2][4], bh[2][2], bl[2][2];
            #pragma unroll
            for (int mi = 0; mi < 2; mi++){
                uint32_t ao = (aRow + mi*16)*144 + kb + aCol*2;
                ldm_x4(ah[mi], base + ao);
                ldm_x4(al[mi], base + MATB + ao);
            }
            #pragma unroll
            for (int ni = 0; ni < 2; ni++){
                uint32_t bo = (bRow + ni*8)*144 + kb + bCol*2;
                ldm_x2(bh[ni], base + 2*MATB + bo);
                ldm_x2(bl[ni], base + 3*MATB + bo);
            }
            #pragma unroll
            for (int mi = 0; mi < 2; mi++)
                #pragma unroll
                for (int ni = 0; ni < 2; ni++){
                    mma_bf16(acc[mi][ni], ah[mi], bh[ni]);
                    mma_bf16(acc[mi][ni], ah[mi], bl[ni]);
                    mma_bf16(acc[mi][ni], al[mi], bh[ni]);
                }
        }
        __syncthreads();
    }
    float* Cs = (float*)sm;
    #pragma unroll
    for (int mi = 0; mi < 2; mi++)
        #pragma unroll
        for (int ni = 0; ni < 2; ni++){
            int r0 = wm*32 + mi*16 + (lane >> 2);
            int c0 = wn*16 + ni*8 + (lane & 3)*2;
            Cs[r0*68 + c0]         = acc[mi][ni][0];
            Cs[r0*68 + c0 + 1]     = acc[mi][ni][1];
            Cs[(r0+8)*68 + c0]     = acc[mi][ni][2];
            Cs[(r0+8)*68 + c0 + 1] = acc[mi][ni][3];
        }
    __syncthreads();
    #pragma unroll
    for (int i = 0; i < 4; i++){
        int idx = tid + i*256;
        int r = idx >> 4, jl = idx & 15;
        *(float4*)&g_y[(size_t)(mb*64 + r)*128 + nb*64 + jl*4] =
            *(const float4*)&Cs[r*68 + jl*4];
    }
}

// ---------------- output transforms ----------------
__global__ void k_out(float* __restrict__ out, const float* __restrict__ bfc){
    int n = blockIdx.x*8 + (threadIdx.x >> 5);
    int lane = threadIdx.x & 31;
    int b = n / 257, t = n - b*257;         // output row n = b*257 + t
    const float* y = g_y + (size_t)(t*256 + b)*128;
    const int N = NROWS;
    float pi = (lane < 20) ? (y[3+lane] + bfc[3+lane]) : -3.4e38f;
    float m = pi;
    #pragma unroll
    for (int o = 16; o; o >>= 1) m = fmaxf(m, __shfl_xor_sync(0xffffffffu, m, o));
    float e = (lane < 20) ? __expf(pi - m) : 0.f;
    float s = e;
    #pragma unroll
    for (int o = 16; o; o >>= 1) s += __shfl_xor_sync(0xffffffffu, s, o);
    float inv = __fdividef(1.f, s);
    if (lane < 20){
        out[           n*20 + lane] = e*inv;
        out[  N*20   + n*20 + lane] = y[23 + lane] + bfc[23 + lane];
        out[2*N*20   + n*20 + lane] = y[43 + lane] + bfc[43 + lane];
        out[3*N*20   + n*20 + lane] = __expf(y[63 + lane] + bfc[63 + lane]);
        out[4*N*20   + n*20 + lane] = __expf(y[83 + lane] + bfc[83 + lane]);
        out[5*N*20   + n*20 + lane] = ftanh(y[103 + lane] + bfc[103 + lane]);
    }
    if (lane < 3)
        out[6*N*20 + n*3 + lane] = y[lane] + bfc[lane];
}

extern "C" void kernel_launch(void* const* d_in, const int* in_sizes, int n_in,
                              void* d_out, int out_size){
    const float* bbf    = (const float*)d_in[0];
    const float* z      = (const float*)d_in[1];
    const float* sk     = (const float*)d_in[2];
    const float* Wfc_hc = (const float*)d_in[3];
    const float* bfc_hc = (const float*)d_in[4];
    const float* Wch    = (const float*)d_in[5];
    const float* bch    = (const float*)d_in[6];
    const float* Kcf    = (const float*)d_in[7];
    const float* bcf    = (const float*)d_in[8];
    const float* Watt   = (const float*)d_in[9];
    const float* batt   = (const float*)d_in[10];
    const float* Wih    = (const float*)d_in[11];
    const float* Whh    = (const float*)d_in[12];
    const float* bih    = (const float*)d_in[13];
    const float* bhh    = (const float*)d_in[14];
    const float* Wfcp   = (const float*)d_in[15];
    const float* bfcp   = (const float*)d_in[16];
    float* out = (float*)d_out;

    cudaFuncSetAttribute(k_gmm,  cudaFuncAttributeMaxDynamicSharedMemorySize, SMEM_GATES);
    cudaFuncSetAttribute(k_cgmm, cudaFuncAttributeMaxDynamicSharedMemorySize, SMEM_GATES);
    cudaFuncSetAttribute(k_pgmm, cudaFuncAttributeMaxDynamicSharedMemorySize, SMEM_GATES);

    k_wc   <<<4608, 256>>>(Kcf);
    k_im2  <<<256, 256>>>(bbf);
    k_wct2 <<<NCOL, 256>>>(Wih, Whh, bih, bhh, Wch);
    k_wfc  <<<128, 256>>>(Wfcp);
    k_init <<<256, 256>>>(z, Wfc_hc, bfc_hc);
    k_cgmm <<<dim3(256, 4), 256, SMEM_GATES>>>(bcf);

    for (int t = 0; t < NSTEP; t++){
        k_gmm<<<dim3(4, 36), 256, SMEM_GATES>>>(0, 0, 8, t, bch);
        k_attn2<<<128, 256>>>(t, Watt, batt, bbf, sk);
        k_gmm<<<dim3(4, 32), 256, SMEM_GATES>>>(2, 8, 9, t, nullptr);
    }
    k_pgmm<<<dim3(1028, 2), 256, SMEM_GATES>>>();
    k_out <<<8224, 256>>>(out, bfcp);
}